// round 11
// baseline (speedup 1.0000x reference)
#include <cuda_runtime.h>
#include <math.h>
#include <stdint.h>
#include <string.h>

#define BSZ   8
#define SEQ   19947
#define MROWS 159576          // BSZ*SEQ
#define CH    256
#define NC    91
#define NTOP  20

// output layout (float32, concatenated flattened tuple)
#define OFF_OUT  0            // (8,20,95)
#define OFF_REF  15200        // (8,20,4)
#define OFF_KEEP 15840        // (8,20)
#define OFF_SC   16000        // (8,20)

// ---------------- scratch (device globals: allocation-free) ----------------
__device__ float g_tmp[MROWS * CH];      // G1 out (pre-LN), later h2
__device__ float g_outmem[MROWS * CH];
__device__ float g_h1[MROWS * CH];
__device__ float g_logits[MROWS * NC];
__device__ float g_scores[MROWS];
__device__ float g_scratch[MROWS];
__device__ float g_prop[MROWS * 4];
__device__ float g_coords[MROWS * 4];
__device__ unsigned char g_rowinv[MROWS];
__device__ int   g_topidx[BSZ * NTOP];
__device__ float g_topsc[BSZ * NTOP];
// pre-transposed, tf32-split weights: rows: [0,256)=W_enc^T, [256,512)=W1^T,
// [512,768)=W2^T, [768,896)=W_cls^T (rows 91..127 of that block zero)
#define BT_ROWS 896
__device__ float g_bt_hi[BT_ROWS * CH];
__device__ float g_bt_lo[BT_ROWS * CH];

__device__ __forceinline__ float tf32_hi(float x) {
    return __uint_as_float(__float_as_uint(x) & 0xFFFFE000u);
}

// one m16n8k8 tf32 mma, D += A*B  (fp32 accumulate)
__device__ __forceinline__ void mma8(float* d, const uint4& a, const uint2& b) {
    asm volatile(
        "mma.sync.aligned.m16n8k8.row.col.f32.tf32.tf32.f32 "
        "{%0,%1,%2,%3}, {%4,%5,%6,%7}, {%8,%9}, {%0,%1,%2,%3};"
        : "+f"(d[0]), "+f"(d[1]), "+f"(d[2]), "+f"(d[3])
        : "r"(a.x), "r"(a.y), "r"(a.z), "r"(a.w), "r"(b.x), "r"(b.y));
}

// ---------------- kernel 0: proposal logits + row invalid flags ------------
__global__ void props_kernel(const unsigned char* __restrict__ mask,
                             unsigned char* __restrict__ rowInv,
                             float* __restrict__ prop)
{
    int row = blockIdx.x * blockDim.x + threadIdx.x;
    if (row >= MROWS) return;
    int s = row % SEQ;
    int Hh, Ww, lvl, t;
    if (s < 15000)      { lvl = 0; Hh = 100; Ww = 150; t = s; }
    else if (s < 18750) { lvl = 1; Hh = 50;  Ww = 75;  t = s - 15000; }
    else if (s < 19700) { lvl = 2; Hh = 25;  Ww = 38;  t = s - 18750; }
    else                { lvl = 3; Hh = 13;  Ww = 19;  t = s - 19700; }
    int y = t / Ww, x = t % Ww;
    float cx = ((float)x + 0.5f) / (float)Ww;
    float cy = ((float)y + 0.5f) / (float)Hh;
    float wh = 0.05f * (float)(1 << lvl);
    bool valid = (cx > 0.01f) && (cx < 0.99f) &&
                 (cy > 0.01f) && (cy < 0.99f) &&
                 (wh > 0.01f) && (wh < 0.99f);
    bool inv = (mask[row] != 0) || !valid;
    rowInv[row] = inv ? 1 : 0;
    if (inv) {
        prop[row*4+0] = INFINITY; prop[row*4+1] = INFINITY;
        prop[row*4+2] = INFINITY; prop[row*4+3] = INFINITY;
    } else {
        float lw = logf(wh / (1.f - wh));
        prop[row*4+0] = logf(cx / (1.f - cx));
        prop[row*4+1] = logf(cy / (1.f - cy));
        prop[row*4+2] = lw;
        prop[row*4+3] = lw;
    }
}

// ---------------- weight transpose + tf32 split (once per launch) ----------
__global__ void wsplit_kernel(const float* __restrict__ We, const float* __restrict__ W1,
                              const float* __restrict__ W2, const float* __restrict__ Wc,
                              float* __restrict__ bth, float* __restrict__ btl)
{
    int idx = blockIdx.x * 256 + threadIdx.x;     // 0 .. BT_ROWS*256-1
    if (idx >= BT_ROWS * CH) return;
    int n = idx >> 8;
    int k = idx & 255;
    float w;
    if (n < 256)      w = We[k * 256 + n];
    else if (n < 512) w = W1[k * 256 + (n - 256)];
    else if (n < 768) w = W2[k * 256 + (n - 512)];
    else { int nn = n - 768; w = (nn < NC) ? Wc[k * NC + nn] : 0.f; }
    float h = tf32_hi(w);
    bth[idx] = h;
    btl[idx] = tf32_hi(w - h);
}

// ---------------- tf32 3-split tensor-core GEMM (mma.sync) ------------------
// C[M, Nreal] = act(A[M,256] @ Bt^T + bias); Bt pre-transposed/split [n][k].
// Block 128x128, 256 threads, warp grid 4x2 (warp tile 32x64).
// SMEM per k-slab (32 k): fragments in mma order.
//   A plane: [4 kstep][8 mtile][32 lane][4 reg]  = 4096 floats (x hi/lo)
//   B plane: [4 kstep][16 ntile][32 lane][2 reg] = 4096 floats (x hi/lo)
// slab = 16384 floats (64KB); double buffered = 128KB dynamic smem.
__global__ void __launch_bounds__(256, 1)
tgemm_kernel(const float* __restrict__ A,
             const float* __restrict__ bth, const float* __restrict__ btl,
             int matOff,
             const float* __restrict__ bias, float* __restrict__ C,
             int M, int Nreal, int act,
             const unsigned char* __restrict__ rowInv,
             float* __restrict__ scores)
{
    extern __shared__ float smf[];
    __shared__ float sred[128];

    const int tid  = threadIdx.x;
    const int warp = tid >> 5, lane = tid & 31;
    const int rowBase = blockIdx.x * 128;
    const int colBase = blockIdx.y * 128;

    // fill assignment: this thread owns A row m (16 k) and B row n=m (16 k)
    const int m   = tid >> 1;
    const int kkb = (tid & 1) * 16;
    const int agr = rowBase + m;
    const bool avalid = (agr < M) && (rowInv == nullptr || rowInv[agr] == 0);
    const float* arow  = A + (size_t)agr * CH;
    const int bn = matOff + colBase + m;
    const float* bhrow = bth + (size_t)bn * CH;
    const float* blrow = btl + (size_t)bn * CH;

    auto fill = [&](int kb, int buf) {
        float* aH = smf + buf * 16384;
        float* aL = aH + 4096;
        float* bH = aH + 8192;
        float* bL = aH + 12288;
        const int kbase = kb * 32;
        const int mtile = m >> 4, mr = m & 15;
        const int ntile = m >> 3, nr = m & 7;
#pragma unroll
        for (int j = 0; j < 4; j++) {
            int kk0 = kkb + j * 4;
            float4 v = avalid ? *reinterpret_cast<const float4*>(arow + kbase + kk0)
                              : make_float4(0.f, 0.f, 0.f, 0.f);
            float xs[4] = {v.x, v.y, v.z, v.w};
            float4 vh = *reinterpret_cast<const float4*>(bhrow + kbase + kk0);
            float4 vl = *reinterpret_cast<const float4*>(blrow + kbase + kk0);
            float hs[4] = {vh.x, vh.y, vh.z, vh.w};
            float ls[4] = {vl.x, vl.y, vl.z, vl.w};
#pragma unroll
            for (int e = 0; e < 4; e++) {
                int kk = kk0 + e;
                int kstep = kk >> 3, kr = kk & 7;
                // A fragment slot
                {
                    float x = xs[e];
                    float h = tf32_hi(x);
                    float l = tf32_hi(x - h);
                    int ln = ((mr & 7) << 2) | (kr & 3);
                    int rg = ((mr >> 3) & 1) | ((kr & 4) >> 1);
                    int idx = ((kstep * 8 + mtile) * 32 + ln) * 4 + rg;
                    aH[idx] = h; aL[idx] = l;
                }
                // B fragment slot
                {
                    int ln = (nr << 2) | (kr & 3);
                    int rg = (kr & 4) >> 2;
                    int idx = ((kstep * 16 + ntile) * 32 + ln) * 2 + rg;
                    bH[idx] = hs[e]; bL[idx] = ls[e];
                }
            }
        }
    };

    const int wr = (warp >> 1) * 32;     // warp row offset in tile
    const int wc = (warp & 1) * 64;      // warp col offset in tile
    const int mt0 = wr >> 4, nt0 = wc >> 3;

    float acc[2][8][4];
#pragma unroll
    for (int mt = 0; mt < 2; mt++)
#pragma unroll
        for (int nt = 0; nt < 8; nt++)
#pragma unroll
            for (int q = 0; q < 4; q++) acc[mt][nt][q] = 0.f;

    fill(0, 0);
    __syncthreads();

#pragma unroll 1
    for (int kb = 0; kb < 8; kb++) {
        const int cur = kb & 1;
        if (kb < 7) fill(kb + 1, cur ^ 1);
        const float* aH = smf + cur * 16384;
        const float* aL = aH + 4096;
        const float* bH = aH + 8192;
        const float* bL = aH + 12288;
#pragma unroll
        for (int ks = 0; ks < 4; ks++) {
            uint4 ahp[2], alp[2];
#pragma unroll
            for (int mt = 0; mt < 2; mt++) {
                int base = ((ks * 8 + mt0 + mt) * 32 + lane) * 4;
                ahp[mt] = *reinterpret_cast<const uint4*>(aH + base);
                alp[mt] = *reinterpret_cast<const uint4*>(aL + base);
            }
            uint2 bhp[8], blp[8];
#pragma unroll
            for (int nt = 0; nt < 8; nt++) {
                int base = ((ks * 16 + nt0 + nt) * 32 + lane) * 2;
                bhp[nt] = *reinterpret_cast<const uint2*>(bH + base);
                blp[nt] = *reinterpret_cast<const uint2*>(bL + base);
            }
#pragma unroll
            for (int mt = 0; mt < 2; mt++)
#pragma unroll
                for (int nt = 0; nt < 8; nt++) {
                    mma8(acc[mt][nt], ahp[mt], bhp[nt]);
                    mma8(acc[mt][nt], ahp[mt], blp[nt]);
                    mma8(acc[mt][nt], alp[mt], bhp[nt]);
                }
        }
        __syncthreads();
    }

    // ---- epilogue ----
    const int gid = lane >> 2, tg = lane & 3;
    float rmax[2][2] = {{-INFINITY, -INFINITY}, {-INFINITY, -INFINITY}};
#pragma unroll
    for (int mt = 0; mt < 2; mt++) {
#pragma unroll
        for (int rh = 0; rh < 2; rh++) {
            int gr = rowBase + wr + mt * 16 + gid + rh * 8;
            if (gr < M) {
#pragma unroll
                for (int nt = 0; nt < 8; nt++) {
                    int gc = colBase + wc + nt * 8 + tg * 2;
                    float v0 = acc[mt][nt][rh * 2 + 0];
                    float v1 = acc[mt][nt][rh * 2 + 1];
                    if (Nreal == 256) {
                        v0 += bias[gc]; v1 += bias[gc + 1];
                        if (act) { v0 = fmaxf(v0, 0.f); v1 = fmaxf(v1, 0.f); }
                        *reinterpret_cast<float2*>(&C[(size_t)gr * 256 + gc]) =
                            make_float2(v0, v1);
                    } else {
                        if (gc < Nreal) {
                            v0 += bias[gc];
                            C[(size_t)gr * Nreal + gc] = v0;
                            rmax[mt][rh] = fmaxf(rmax[mt][rh], v0);
                        }
                        if (gc + 1 < Nreal) {
                            v1 += bias[gc + 1];
                            C[(size_t)gr * Nreal + gc + 1] = v1;
                            rmax[mt][rh] = fmaxf(rmax[mt][rh], v1);
                        }
                    }
                }
            }
        }
    }

    // ---- fused row-max (cls GEMM) ----
    if (scores != nullptr) {
#pragma unroll
        for (int mt = 0; mt < 2; mt++)
#pragma unroll
            for (int rh = 0; rh < 2; rh++) {
                float r = rmax[mt][rh];
                r = fmaxf(r, __shfl_xor_sync(0xffffffffu, r, 1));
                r = fmaxf(r, __shfl_xor_sync(0xffffffffu, r, 2));
                rmax[mt][rh] = r;
                int lrow = wr + mt * 16 + gid + rh * 8;
                if ((warp & 1) == 0 && tg == 0) sred[lrow] = r;
            }
        __syncthreads();
#pragma unroll
        for (int mt = 0; mt < 2; mt++)
#pragma unroll
            for (int rh = 0; rh < 2; rh++) {
                int lrow = wr + mt * 16 + gid + rh * 8;
                int gr = rowBase + lrow;
                if ((warp & 1) == 1 && tg == 0 && gr < M)
                    scores[gr] = fmaxf(rmax[mt][rh], sred[lrow]);
            }
    }
}

// ---------------- LayerNorm (warp per row) ----------------------------------
__global__ void ln_kernel(const float* __restrict__ X, const float* __restrict__ g,
                          const float* __restrict__ b, float* __restrict__ Y)
{
    int row = (blockIdx.x * blockDim.x + threadIdx.x) >> 5;
    if (row >= MROWS) return;
    int lane = threadIdx.x & 31;
    const float* x = X + (size_t)row * CH + lane * 8;
    float4 v0 = *reinterpret_cast<const float4*>(x);
    float4 v1 = *reinterpret_cast<const float4*>(x + 4);
    float s = v0.x+v0.y+v0.z+v0.w + v1.x+v1.y+v1.z+v1.w;
#pragma unroll
    for (int off = 16; off; off >>= 1) s += __shfl_xor_sync(0xffffffffu, s, off);
    float mean = s * (1.f / 256.f);
    float d0 = v0.x-mean, d1 = v0.y-mean, d2 = v0.z-mean, d3 = v0.w-mean;
    float d4 = v1.x-mean, d5 = v1.y-mean, d6 = v1.z-mean, d7 = v1.w-mean;
    float q = d0*d0+d1*d1+d2*d2+d3*d3+d4*d4+d5*d5+d6*d6+d7*d7;
#pragma unroll
    for (int off = 16; off; off >>= 1) q += __shfl_xor_sync(0xffffffffu, q, off);
    float var = q * (1.f / 256.f);
    float inv = 1.f / sqrtf(var + 1e-5f);
    float4 gg0 = *reinterpret_cast<const float4*>(g + lane * 8);
    float4 gg1 = *reinterpret_cast<const float4*>(g + lane * 8 + 4);
    float4 bb0 = *reinterpret_cast<const float4*>(b + lane * 8);
    float4 bb1 = *reinterpret_cast<const float4*>(b + lane * 8 + 4);
    float4 o0, o1;
    o0.x = d0*inv*gg0.x + bb0.x; o0.y = d1*inv*gg0.y + bb0.y;
    o0.z = d2*inv*gg0.z + bb0.z; o0.w = d3*inv*gg0.w + bb0.w;
    o1.x = d4*inv*gg1.x + bb1.x; o1.y = d5*inv*gg1.y + bb1.y;
    o1.z = d6*inv*gg1.z + bb1.z; o1.w = d7*inv*gg1.w + bb1.w;
    float* y = Y + (size_t)row * CH + lane * 8;
    *reinterpret_cast<float4*>(y) = o0;
    *reinterpret_cast<float4*>(y + 4) = o1;
}

// ---------------- coords = h2 @ W3 + b3 + prop (warp per row) ---------------
__global__ void coords_kernel(const float* __restrict__ H2, const float* __restrict__ W3,
                              const float* __restrict__ b3, const float* __restrict__ prop,
                              float* __restrict__ out)
{
    int row = (blockIdx.x * blockDim.x + threadIdx.x) >> 5;
    if (row >= MROWS) return;
    int lane = threadIdx.x & 31;
    const float* h = H2 + (size_t)row * CH;
    float4 acc = make_float4(0.f, 0.f, 0.f, 0.f);
    for (int k = lane; k < CH; k += 32) {
        float a = h[k];
        float4 w = *reinterpret_cast<const float4*>(W3 + k * 4);
        acc.x = fmaf(a, w.x, acc.x); acc.y = fmaf(a, w.y, acc.y);
        acc.z = fmaf(a, w.z, acc.z); acc.w = fmaf(a, w.w, acc.w);
    }
#pragma unroll
    for (int off = 16; off; off >>= 1) {
        acc.x += __shfl_xor_sync(0xffffffffu, acc.x, off);
        acc.y += __shfl_xor_sync(0xffffffffu, acc.y, off);
        acc.z += __shfl_xor_sync(0xffffffffu, acc.z, off);
        acc.w += __shfl_xor_sync(0xffffffffu, acc.w, off);
    }
    if (lane == 0) {
        out[row*4+0] = acc.x + b3[0] + prop[row*4+0];
        out[row*4+1] = acc.y + b3[1] + prop[row*4+1];
        out[row*4+2] = acc.z + b3[2] + prop[row*4+2];
        out[row*4+3] = acc.w + b3[3] + prop[row*4+3];
    }
}

// ---------------- top-20 per batch (block per batch) -------------------------
__global__ void topk_kernel(const float* __restrict__ scores, float* __restrict__ scratch,
                            int* __restrict__ topIdx, float* __restrict__ topSc)
{
    int b = blockIdx.x, tid = threadIdx.x;
    const float* s = scores + b * SEQ;
    float* t = scratch + b * SEQ;
    for (int i = tid; i < SEQ; i += blockDim.x) t[i] = s[i];
    __syncthreads();
    __shared__ float rv[1024];
    __shared__ int   ri[1024];
    for (int it = 0; it < NTOP; it++) {
        float bv = -INFINITY; int bi = 0x7fffffff;
        for (int i = tid; i < SEQ; i += blockDim.x) {
            float v = t[i];
            if (v > bv) { bv = v; bi = i; }
        }
        rv[tid] = bv; ri[tid] = bi;
        __syncthreads();
        for (int off = 512; off > 0; off >>= 1) {
            if (tid < off) {
                float ov = rv[tid + off]; int oi = ri[tid + off];
                if (ov > rv[tid] || (ov == rv[tid] && oi < ri[tid])) { rv[tid] = ov; ri[tid] = oi; }
            }
            __syncthreads();
        }
        if (tid == 0) {
            topIdx[b * NTOP + it] = ri[0];
            topSc[b * NTOP + it]  = rv[0];
            t[ri[0]] = -INFINITY;
        }
        __syncthreads();
    }
}

// ---------------- final: gather + sigmoid + boxes + NMS ----------------------
__global__ void final_kernel(const float* __restrict__ logits, const float* __restrict__ coords,
                             const int* __restrict__ topIdx, const float* __restrict__ topSc,
                             const float* __restrict__ WH, float* __restrict__ out)
{
    int b = blockIdx.x, tid = threadIdx.x;
    __shared__ int   idxs[NTOP];
    __shared__ float refp[NTOP][4];
    __shared__ float boxes[NTOP][4];
    if (tid < NTOP) idxs[tid] = topIdx[b * NTOP + tid];
    __syncthreads();

    for (int o = tid; o < NTOP * NC; o += blockDim.x) {
        int k = o / NC, c = o % NC;
        size_t row = (size_t)b * SEQ + idxs[k];
        out[OFF_OUT + b * (NTOP * (NC + 4)) + k * (NC + 4) + c] = logits[row * NC + c];
    }
    if (tid < NTOP * 4) {
        int k = tid >> 2, c = tid & 3;
        size_t row = (size_t)b * SEQ + idxs[k];
        float v = coords[row * 4 + c];
        out[OFF_OUT + b * (NTOP * (NC + 4)) + k * (NC + 4) + NC + c] = v;
        float r = 1.f / (1.f + expf(-v));
        out[OFF_REF + b * (NTOP * 4) + k * 4 + c] = r;
        refp[k][c] = r;
    }
    if (tid < NTOP) out[OFF_SC + b * NTOP + tid] = topSc[b * NTOP + tid];
    __syncthreads();
    if (tid < NTOP) {
        float cx = refp[tid][0], cy = refp[tid][1], w = refp[tid][2], h = refp[tid][3];
        boxes[tid][0] = truncf((cx - 0.5f * w) * WH[b * 4 + 0]);
        boxes[tid][1] = truncf((cy - 0.5f * h) * WH[b * 4 + 1]);
        boxes[tid][2] = truncf((cx + 0.5f * w) * WH[b * 4 + 2]);
        boxes[tid][3] = truncf((cy + 0.5f * h) * WH[b * 4 + 3]);
    }
    __syncthreads();
    if (tid == 0) {
        bool supp[NTOP];
        float area[NTOP];
        for (int k = 0; k < NTOP; k++) {
            supp[k] = false;
            area[k] = (boxes[k][2] - boxes[k][0]) * (boxes[k][3] - boxes[k][1]);
        }
        for (int i = 0; i < NTOP; i++) {
            if (supp[i]) continue;
            for (int j = i + 1; j < NTOP; j++) {
                float xx1 = fmaxf(boxes[i][0], boxes[j][0]);
                float yy1 = fmaxf(boxes[i][1], boxes[j][1]);
                float xx2 = fminf(boxes[i][2], boxes[j][2]);
                float yy2 = fminf(boxes[i][3], boxes[j][3]);
                float inter = fmaxf(xx2 - xx1, 0.f) * fmaxf(yy2 - yy1, 0.f);
                float iou = inter / (area[i] + area[j] - inter);
                if (iou > 0.5f) supp[j] = true;
            }
        }
        for (int k = 0; k < NTOP; k++)
            out[OFF_KEEP + b * NTOP + k] = supp[k] ? 0.f : 1.f;
    }
}

// ---------------- launch -----------------------------------------------------
extern "C" void kernel_launch(void* const* d_in, const int* in_sizes, int n_in,
                              void* d_out, int out_size)
{
    const float* memory        = (const float*)d_in[0];
    const unsigned char* mask  = (const unsigned char*)d_in[1];
    const float* WH            = (const float*)d_in[2];
    const float* W_enc         = (const float*)d_in[3];
    const float* b_enc         = (const float*)d_in[4];
    const float* ln_g          = (const float*)d_in[5];
    const float* ln_b          = (const float*)d_in[6];
    const float* W_cls         = (const float*)d_in[7];
    const float* b_cls         = (const float*)d_in[8];
    const float* W1            = (const float*)d_in[9];
    const float* b1            = (const float*)d_in[10];
    const float* W2            = (const float*)d_in[11];
    const float* b2            = (const float*)d_in[12];
    const float* W3            = (const float*)d_in[13];
    const float* b3            = (const float*)d_in[14];
    float* out = (float*)d_out;

    float *p_tmp, *p_outmem, *p_h1, *p_logits, *p_scores, *p_scratch, *p_prop, *p_coords, *p_topsc;
    float *p_bth, *p_btl;
    unsigned char* p_rowinv; int* p_topidx;
    cudaGetSymbolAddress((void**)&p_tmp,     g_tmp);
    cudaGetSymbolAddress((void**)&p_outmem,  g_outmem);
    cudaGetSymbolAddress((void**)&p_h1,      g_h1);
    cudaGetSymbolAddress((void**)&p_logits,  g_logits);
    cudaGetSymbolAddress((void**)&p_scores,  g_scores);
    cudaGetSymbolAddress((void**)&p_scratch, g_scratch);
    cudaGetSymbolAddress((void**)&p_prop,    g_prop);
    cudaGetSymbolAddress((void**)&p_coords,  g_coords);
    cudaGetSymbolAddress((void**)&p_rowinv,  g_rowinv);
    cudaGetSymbolAddress((void**)&p_topidx,  g_topidx);
    cudaGetSymbolAddress((void**)&p_topsc,   g_topsc);
    cudaGetSymbolAddress((void**)&p_bth,     g_bt_hi);
    cudaGetSymbolAddress((void**)&p_btl,     g_bt_lo);

    const int SMEM_T = 2 * 16384 * 4;   // 131072 bytes (two 64KB slabs)
    cudaFuncSetAttribute(tgemm_kernel, cudaFuncAttributeMaxDynamicSharedMemorySize, SMEM_T);

    props_kernel<<<(MROWS + 255) / 256, 256>>>(mask, p_rowinv, p_prop);
    wsplit_kernel<<<(BT_ROWS * CH + 255) / 256, 256>>>(W_enc, W1, W2, W_cls, p_bth, p_btl);

    const int gRows = (MROWS + 127) / 128;   // 1247
    dim3 gFull(gRows, 2), gCls(gRows, 1);
    // tmp = mem_masked @ W_enc + b_enc
    tgemm_kernel<<<gFull, 256, SMEM_T>>>(memory, p_bth, p_btl, 0,   b_enc, p_tmp,
                                         MROWS, 256, 0, p_rowinv, nullptr);
    // out_mem = LN(tmp)*g + b
    ln_kernel<<<MROWS / 8, 256>>>(p_tmp, ln_g, ln_b, p_outmem);
    // h1 = relu(out_mem @ W1 + b1)
    tgemm_kernel<<<gFull, 256, SMEM_T>>>(p_outmem, p_bth, p_btl, 256, b1, p_h1,
                                         MROWS, 256, 1, nullptr, nullptr);
    // h2 = relu(h1 @ W2 + b2)  (reuse tmp)
    tgemm_kernel<<<gFull, 256, SMEM_T>>>(p_h1, p_bth, p_btl, 512, b2, p_tmp,
                                         MROWS, 256, 1, nullptr, nullptr);
    // logits = out_mem @ W_cls + b_cls, fused row-max -> scores
    tgemm_kernel<<<gCls, 256, SMEM_T>>>(p_outmem, p_bth, p_btl, 768, b_cls, p_logits,
                                        MROWS, NC, 0, nullptr, p_scores);
    // coords = h2 @ W3 + b3 + prop
    coords_kernel<<<SEQ, 256>>>(p_tmp, W3, b3, p_prop, p_coords);
    // top-20 per batch
    topk_kernel<<<BSZ, 1024>>>(p_scores, p_scratch, p_topidx, p_topsc);
    // gather + sigmoid + NMS + writes
    final_kernel<<<BSZ, 128>>>(p_logits, p_coords, p_topidx, p_topsc, WH, out);

    (void)in_sizes; (void)n_in; (void)out_size;
}

// round 12
// speedup vs baseline: 3.1013x; 3.1013x over previous
#include <cuda_runtime.h>
#include <math.h>
#include <stdint.h>
#include <string.h>

#define BSZ   8
#define SEQ   19947
#define MROWS 159576          // BSZ*SEQ
#define CH    256
#define NC    91
#define NTOP  20

// output layout (float32, concatenated flattened tuple)
#define OFF_OUT  0            // (8,20,95)
#define OFF_REF  15200        // (8,20,4)
#define OFF_KEEP 15840        // (8,20)
#define OFF_SC   16000        // (8,20)

// ---------------- scratch (device globals: allocation-free) ----------------
__device__ float g_tmp[MROWS * CH];      // GEMM1 out (pre-LN)
__device__ float g_outmem[MROWS * CH];
__device__ float g_logits[MROWS * NC];
__device__ float g_scores[MROWS];
__device__ float g_scratch[MROWS];
__device__ unsigned char g_rowinv[MROWS];
__device__ int   g_topidx[BSZ * NTOP];
__device__ float g_topsc[BSZ * NTOP];
__device__ float g_ctop[BSZ * NTOP * 4];

// ---------------- packed f32x2 helpers (Blackwell FFMA2) -------------------
__device__ __forceinline__ unsigned long long ffma2(unsigned long long a,
                                                    unsigned long long b,
                                                    unsigned long long c)
{
    unsigned long long d;
    asm("fma.rn.f32x2 %0, %1, %2, %3;" : "=l"(d) : "l"(a), "l"(b), "l"(c));
    return d;
}
__device__ __forceinline__ unsigned long long bcast2(float x)
{
    unsigned long long d;
    unsigned int xi = __float_as_uint(x);
    asm("mov.b64 %0, {%1, %1};" : "=l"(d) : "r"(xi));
    return d;
}
__device__ __forceinline__ float pickhalf(unsigned long long v, int half)
{
    float2 p;
    memcpy(&p, &v, 8);
    return half ? p.y : p.x;
}

// ---------------- kernel 0: row invalid flags --------------------------------
__global__ void props_kernel(const unsigned char* __restrict__ mask,
                             unsigned char* __restrict__ rowInv)
{
    int row = blockIdx.x * blockDim.x + threadIdx.x;
    if (row >= MROWS) return;
    int s = row % SEQ;
    int Hh, Ww, t;
    if (s < 15000)      { Hh = 100; Ww = 150; t = s; }
    else if (s < 18750) { Hh = 50;  Ww = 75;  t = s - 15000; }
    else if (s < 19700) { Hh = 25;  Ww = 38;  t = s - 18750; }
    else                { Hh = 13;  Ww = 19;  t = s - 19700; }
    int y = t / Ww, x = t % Ww;
    float cx = ((float)x + 0.5f) / (float)Ww;
    float cy = ((float)y + 0.5f) / (float)Hh;
    bool valid = (cx > 0.01f) && (cx < 0.99f) &&
                 (cy > 0.01f) && (cy < 0.99f);   // wh in (0.05,0.4): always valid
    rowInv[row] = ((mask[row] != 0) || !valid) ? 1 : 0;
}

// ---------------- SGEMM: C = act(A[M,256] @ B[256,N] + bias) ---------------
// 128x128 block tile, 256 threads, 8x8 microtile, packed f32x2 accumulators.
__device__ __forceinline__ float4 loadA4(const float* __restrict__ A, int gr, int kOff,
                                         int M, const unsigned char* __restrict__ rowInv)
{
    if (gr < M && (rowInv == nullptr || rowInv[gr] == 0))
        return *reinterpret_cast<const float4*>(A + (size_t)gr * CH + kOff);
    return make_float4(0.f, 0.f, 0.f, 0.f);
}
__device__ __forceinline__ float4 loadB4(const float* __restrict__ Bm, int k, int gc, int N)
{
    if ((N & 3) == 0 && gc + 3 < N)
        return *reinterpret_cast<const float4*>(Bm + (size_t)k * N + gc);
    float4 v;
    v.x = (gc + 0 < N) ? Bm[(size_t)k * N + gc + 0] : 0.f;
    v.y = (gc + 1 < N) ? Bm[(size_t)k * N + gc + 1] : 0.f;
    v.z = (gc + 2 < N) ? Bm[(size_t)k * N + gc + 2] : 0.f;
    v.w = (gc + 3 < N) ? Bm[(size_t)k * N + gc + 3] : 0.f;
    return v;
}

__global__ void __launch_bounds__(256, 2)
sgemm2_kernel(const float* __restrict__ A, const float* __restrict__ Bm,
              const float* __restrict__ bias, float* __restrict__ C,
              int M, int N, int act, const unsigned char* __restrict__ rowInv,
              float* __restrict__ scores)
{
    __shared__ float As[2][16][128 + 4];
    __shared__ float Bs[2][16][128 + 4];

    const int tid = threadIdx.x;
    const int rowBase = blockIdx.x * 128;
    const int colBase = blockIdx.y * 128;

    const int warp = tid >> 5, lane = tid & 31;
    const int tRow = (warp & 3) * 32 + (lane & 3) * 8;   // 8 rows (4 packed pairs)
    const int tCol = (warp >> 2) * 64 + (lane >> 2) * 8; // 8 cols

    const int aRow0 = tid >> 2, aK = (tid & 3) << 2, aRow1 = aRow0 + 64;
    const int bK0 = tid >> 5, bN = (tid & 31) << 2, bK1 = bK0 + 8;

    unsigned long long acc2[4][8];
#pragma unroll
    for (int r = 0; r < 4; r++)
#pragma unroll
        for (int c = 0; c < 8; c++) acc2[r][c] = 0ull;

    float4 a0r = loadA4(A, rowBase + aRow0, aK, M, rowInv);
    float4 a1r = loadA4(A, rowBase + aRow1, aK, M, rowInv);
    float4 b0r = loadB4(Bm, bK0, colBase + bN, N);
    float4 b1r = loadB4(Bm, bK1, colBase + bN, N);
    As[0][aK+0][aRow0] = a0r.x; As[0][aK+1][aRow0] = a0r.y;
    As[0][aK+2][aRow0] = a0r.z; As[0][aK+3][aRow0] = a0r.w;
    As[0][aK+0][aRow1] = a1r.x; As[0][aK+1][aRow1] = a1r.y;
    As[0][aK+2][aRow1] = a1r.z; As[0][aK+3][aRow1] = a1r.w;
    *reinterpret_cast<float4*>(&Bs[0][bK0][bN]) = b0r;
    *reinterpret_cast<float4*>(&Bs[0][bK1][bN]) = b1r;
    __syncthreads();

#pragma unroll 1
    for (int kb = 0; kb < 16; kb++) {
        const int cur = kb & 1;
        if (kb < 15) {
            a0r = loadA4(A, rowBase + aRow0, (kb + 1) * 16 + aK, M, rowInv);
            a1r = loadA4(A, rowBase + aRow1, (kb + 1) * 16 + aK, M, rowInv);
            b0r = loadB4(Bm, (kb + 1) * 16 + bK0, colBase + bN, N);
            b1r = loadB4(Bm, (kb + 1) * 16 + bK1, colBase + bN, N);
        }
#pragma unroll
        for (int kk = 0; kk < 16; kk++) {
            ulonglong2 a01 = *reinterpret_cast<const ulonglong2*>(&As[cur][kk][tRow]);
            ulonglong2 a23 = *reinterpret_cast<const ulonglong2*>(&As[cur][kk][tRow + 4]);
            float4 b0 = *reinterpret_cast<const float4*>(&Bs[cur][kk][tCol]);
            float4 b1 = *reinterpret_cast<const float4*>(&Bs[cur][kk][tCol + 4]);
            unsigned long long av[4] = {a01.x, a01.y, a23.x, a23.y};
            float bf[8] = {b0.x, b0.y, b0.z, b0.w, b1.x, b1.y, b1.z, b1.w};
#pragma unroll
            for (int c = 0; c < 8; c++) {
                unsigned long long bc = bcast2(bf[c]);
#pragma unroll
                for (int r = 0; r < 4; r++)
                    acc2[r][c] = ffma2(av[r], bc, acc2[r][c]);
            }
        }
        if (kb < 15) {
            const int nxt = 1 - cur;
            As[nxt][aK+0][aRow0] = a0r.x; As[nxt][aK+1][aRow0] = a0r.y;
            As[nxt][aK+2][aRow0] = a0r.z; As[nxt][aK+3][aRow0] = a0r.w;
            As[nxt][aK+0][aRow1] = a1r.x; As[nxt][aK+1][aRow1] = a1r.y;
            As[nxt][aK+2][aRow1] = a1r.z; As[nxt][aK+3][aRow1] = a1r.w;
            *reinterpret_cast<float4*>(&Bs[nxt][bK0][bN]) = b0r;
            *reinterpret_cast<float4*>(&Bs[nxt][bK1][bN]) = b1r;
            __syncthreads();
        }
    }

    // ---- epilogue: bias + optional relu, vectorized when possible ----
    const int gcBase = colBase + tCol;
    if ((N & 3) == 0 && gcBase + 7 < N) {
        float4 bb0 = *reinterpret_cast<const float4*>(&bias[gcBase]);
        float4 bb1 = *reinterpret_cast<const float4*>(&bias[gcBase + 4]);
#pragma unroll
        for (int r2 = 0; r2 < 4; r2++) {
#pragma unroll
            for (int half = 0; half < 2; half++) {
                int gr = rowBase + tRow + 2 * r2 + half;
                if (gr >= M) continue;
                float4 v0, v1;
                v0.x = pickhalf(acc2[r2][0], half) + bb0.x;
                v0.y = pickhalf(acc2[r2][1], half) + bb0.y;
                v0.z = pickhalf(acc2[r2][2], half) + bb0.z;
                v0.w = pickhalf(acc2[r2][3], half) + bb0.w;
                v1.x = pickhalf(acc2[r2][4], half) + bb1.x;
                v1.y = pickhalf(acc2[r2][5], half) + bb1.y;
                v1.z = pickhalf(acc2[r2][6], half) + bb1.z;
                v1.w = pickhalf(acc2[r2][7], half) + bb1.w;
                if (act) {
                    v0.x = fmaxf(v0.x, 0.f); v0.y = fmaxf(v0.y, 0.f);
                    v0.z = fmaxf(v0.z, 0.f); v0.w = fmaxf(v0.w, 0.f);
                    v1.x = fmaxf(v1.x, 0.f); v1.y = fmaxf(v1.y, 0.f);
                    v1.z = fmaxf(v1.z, 0.f); v1.w = fmaxf(v1.w, 0.f);
                }
                *reinterpret_cast<float4*>(&C[(size_t)gr * N + gcBase]) = v0;
                *reinterpret_cast<float4*>(&C[(size_t)gr * N + gcBase + 4]) = v1;
            }
        }
    } else {
#pragma unroll
        for (int r2 = 0; r2 < 4; r2++) {
#pragma unroll
            for (int half = 0; half < 2; half++) {
                int gr = rowBase + tRow + 2 * r2 + half;
                if (gr >= M) continue;
#pragma unroll
                for (int c = 0; c < 8; c++) {
                    int gc = gcBase + c;
                    if (gc >= N) continue;
                    float v = pickhalf(acc2[r2][c], half) + bias[gc];
                    if (act) v = fmaxf(v, 0.f);
                    C[(size_t)gr * N + gc] = v;
                }
            }
        }
    }

    // ---- fused row-max (cls GEMM: whole N fits in one column-block) ----
    if (scores != nullptr) {
        __syncthreads();                       // all warps done reading As
        float* red = &As[0][0][0];             // reuse as [128][16]
        int slot = ((warp >> 2) << 3) | (lane >> 2);
#pragma unroll
        for (int r2 = 0; r2 < 4; r2++) {
#pragma unroll
            for (int half = 0; half < 2; half++) {
                int lr = tRow + 2 * r2 + half;
                float m = -INFINITY;
#pragma unroll
                for (int c = 0; c < 8; c++) {
                    int gc = gcBase + c;
                    if (gc < N)
                        m = fmaxf(m, pickhalf(acc2[r2][c], half) + bias[gc]);
                }
                red[lr * 16 + slot] = m;
            }
        }
        __syncthreads();
        if (tid < 128) {
            int gr = rowBase + tid;
            if (gr < M) {
                float m = -INFINITY;
#pragma unroll
                for (int s = 0; s < 16; s++) m = fmaxf(m, red[tid * 16 + s]);
                scores[gr] = m;
            }
        }
    }
}

// ---------------- LayerNorm (warp per row) ----------------------------------
__global__ void ln_kernel(const float* __restrict__ X, const float* __restrict__ g,
                          const float* __restrict__ b, float* __restrict__ Y)
{
    int row = (blockIdx.x * blockDim.x + threadIdx.x) >> 5;
    if (row >= MROWS) return;
    int lane = threadIdx.x & 31;
    const float* x = X + (size_t)row * CH + lane * 8;
    float4 v0 = *reinterpret_cast<const float4*>(x);
    float4 v1 = *reinterpret_cast<const float4*>(x + 4);
    float s = v0.x+v0.y+v0.z+v0.w + v1.x+v1.y+v1.z+v1.w;
#pragma unroll
    for (int off = 16; off; off >>= 1) s += __shfl_xor_sync(0xffffffffu, s, off);
    float mean = s * (1.f / 256.f);
    float d0 = v0.x-mean, d1 = v0.y-mean, d2 = v0.z-mean, d3 = v0.w-mean;
    float d4 = v1.x-mean, d5 = v1.y-mean, d6 = v1.z-mean, d7 = v1.w-mean;
    float q = d0*d0+d1*d1+d2*d2+d3*d3+d4*d4+d5*d5+d6*d6+d7*d7;
#pragma unroll
    for (int off = 16; off; off >>= 1) q += __shfl_xor_sync(0xffffffffu, q, off);
    float var = q * (1.f / 256.f);
    float inv = 1.f / sqrtf(var + 1e-5f);
    float4 gg0 = *reinterpret_cast<const float4*>(g + lane * 8);
    float4 gg1 = *reinterpret_cast<const float4*>(g + lane * 8 + 4);
    float4 bb0 = *reinterpret_cast<const float4*>(b + lane * 8);
    float4 bb1 = *reinterpret_cast<const float4*>(b + lane * 8 + 4);
    float4 o0, o1;
    o0.x = d0*inv*gg0.x + bb0.x; o0.y = d1*inv*gg0.y + bb0.y;
    o0.z = d2*inv*gg0.z + bb0.z; o0.w = d3*inv*gg0.w + bb0.w;
    o1.x = d4*inv*gg1.x + bb1.x; o1.y = d5*inv*gg1.y + bb1.y;
    o1.z = d6*inv*gg1.z + bb1.z; o1.w = d7*inv*gg1.w + bb1.w;
    float* y = Y + (size_t)row * CH + lane * 8;
    *reinterpret_cast<float4*>(y) = o0;
    *reinterpret_cast<float4*>(y + 4) = o1;
}

// ---------------- top-20 per batch (block per batch) -------------------------
__global__ void topk_kernel(const float* __restrict__ scores, float* __restrict__ scratch,
                            int* __restrict__ topIdx, float* __restrict__ topSc)
{
    int b = blockIdx.x, tid = threadIdx.x;
    const float* s = scores + b * SEQ;
    float* t = scratch + b * SEQ;
    for (int i = tid; i < SEQ; i += blockDim.x) t[i] = s[i];
    __syncthreads();
    __shared__ float rv[1024];
    __shared__ int   ri[1024];
    for (int it = 0; it < NTOP; it++) {
        float bv = -INFINITY; int bi = 0x7fffffff;
        for (int i = tid; i < SEQ; i += blockDim.x) {
            float v = t[i];
            if (v > bv) { bv = v; bi = i; }
        }
        rv[tid] = bv; ri[tid] = bi;
        __syncthreads();
        for (int off = 512; off > 0; off >>= 1) {
            if (tid < off) {
                float ov = rv[tid + off]; int oi = ri[tid + off];
                if (ov > rv[tid] || (ov == rv[tid] && oi < ri[tid])) { rv[tid] = ov; ri[tid] = oi; }
            }
            __syncthreads();
        }
        if (tid == 0) {
            topIdx[b * NTOP + it] = ri[0];
            topSc[b * NTOP + it]  = rv[0];
            t[ri[0]] = -INFINITY;
        }
        __syncthreads();
    }
}

// ---------------- tiny MLP on top-k rows only --------------------------------
// coordsTop[b,k,:] = h2(h1(out_mem_row)) @ W3 + b3 + prop(row)
__global__ void tinymlp_kernel(const float* __restrict__ outmem,
                               const unsigned char* __restrict__ mask,
                               const float* __restrict__ W1, const float* __restrict__ b1,
                               const float* __restrict__ W2, const float* __restrict__ b2,
                               const float* __restrict__ W3, const float* __restrict__ b3,
                               const int* __restrict__ topIdx,
                               float* __restrict__ coordsTop)
{
    __shared__ float s0[256], s1[256];
    const int blk = blockIdx.x;               // 0..159
    const int b = blk / NTOP;
    const int s = topIdx[blk];                // within-batch index
    const size_t row = (size_t)b * SEQ + s;
    const int tid = threadIdx.x;

    s0[tid] = outmem[row * CH + tid];
    __syncthreads();

    float acc = 0.f;
#pragma unroll 8
    for (int kk = 0; kk < CH; kk++) acc = fmaf(s0[kk], W1[kk * CH + tid], acc);
    s1[tid] = fmaxf(acc + b1[tid], 0.f);
    __syncthreads();

    acc = 0.f;
#pragma unroll 8
    for (int kk = 0; kk < CH; kk++) acc = fmaf(s1[kk], W2[kk * CH + tid], acc);
    float h2 = fmaxf(acc + b2[tid], 0.f);
    __syncthreads();          // all h1 reads of s1 done; s0 reads long done
    s0[tid] = h2;
    __syncthreads();

    const int warp = tid >> 5, lane = tid & 31;
    if (warp < 4) {
        float a = 0.f;
        for (int kk = lane; kk < CH; kk += 32)
            a = fmaf(s0[kk], W3[kk * 4 + warp], a);
#pragma unroll
        for (int off = 16; off; off >>= 1) a += __shfl_xor_sync(0xffffffffu, a, off);
        if (lane == 0) {
            // proposal logit for this row, component `warp`
            int Hh, Ww, t;
            if (s < 15000)      { Hh = 100; Ww = 150; t = s; }
            else if (s < 18750) { Hh = 50;  Ww = 75;  t = s - 15000; }
            else if (s < 19700) { Hh = 25;  Ww = 38;  t = s - 18750; }
            else                { Hh = 13;  Ww = 19;  t = s - 19700; }
            int lvl = (s < 15000) ? 0 : (s < 18750) ? 1 : (s < 19700) ? 2 : 3;
            int y = t / Ww, x = t % Ww;
            float cx = ((float)x + 0.5f) / (float)Ww;
            float cy = ((float)y + 0.5f) / (float)Hh;
            float wh = 0.05f * (float)(1 << lvl);
            bool valid = (cx > 0.01f) && (cx < 0.99f) &&
                         (cy > 0.01f) && (cy < 0.99f);
            bool inv = (mask[row] != 0) || !valid;
            float pv;
            if (inv) pv = INFINITY;
            else {
                float comp = (warp == 0) ? cx : (warp == 1) ? cy : wh;
                pv = logf(comp / (1.f - comp));
            }
            coordsTop[blk * 4 + warp] = a + b3[warp] + pv;
        }
    }
}

// ---------------- final: gather + sigmoid + boxes + NMS ----------------------
__global__ void final_kernel(const float* __restrict__ logits,
                             const float* __restrict__ coordsTop,
                             const int* __restrict__ topIdx, const float* __restrict__ topSc,
                             const float* __restrict__ WH, float* __restrict__ out)
{
    int b = blockIdx.x, tid = threadIdx.x;
    __shared__ int   idxs[NTOP];
    __shared__ float refp[NTOP][4];
    __shared__ float boxes[NTOP][4];
    if (tid < NTOP) idxs[tid] = topIdx[b * NTOP + tid];
    __syncthreads();

    for (int o = tid; o < NTOP * NC; o += blockDim.x) {
        int k = o / NC, c = o % NC;
        size_t row = (size_t)b * SEQ + idxs[k];
        out[OFF_OUT + b * (NTOP * (NC + 4)) + k * (NC + 4) + c] = logits[row * NC + c];
    }
    if (tid < NTOP * 4) {
        int k = tid >> 2, c = tid & 3;
        float v = coordsTop[(b * NTOP + k) * 4 + c];
        out[OFF_OUT + b * (NTOP * (NC + 4)) + k * (NC + 4) + NC + c] = v;
        float r = 1.f / (1.f + expf(-v));
        out[OFF_REF + b * (NTOP * 4) + k * 4 + c] = r;
        refp[k][c] = r;
    }
    if (tid < NTOP) out[OFF_SC + b * NTOP + tid] = topSc[b * NTOP + tid];
    __syncthreads();
    if (tid < NTOP) {
        float cx = refp[tid][0], cy = refp[tid][1], w = refp[tid][2], h = refp[tid][3];
        boxes[tid][0] = truncf((cx - 0.5f * w) * WH[b * 4 + 0]);
        boxes[tid][1] = truncf((cy - 0.5f * h) * WH[b * 4 + 1]);
        boxes[tid][2] = truncf((cx + 0.5f * w) * WH[b * 4 + 2]);
        boxes[tid][3] = truncf((cy + 0.5f * h) * WH[b * 4 + 3]);
    }
    __syncthreads();
    if (tid == 0) {
        bool supp[NTOP];
        float area[NTOP];
        for (int k = 0; k < NTOP; k++) {
            supp[k] = false;
            area[k] = (boxes[k][2] - boxes[k][0]) * (boxes[k][3] - boxes[k][1]);
        }
        for (int i = 0; i < NTOP; i++) {
            if (supp[i]) continue;
            for (int j = i + 1; j < NTOP; j++) {
                float xx1 = fmaxf(boxes[i][0], boxes[j][0]);
                float yy1 = fmaxf(boxes[i][1], boxes[j][1]);
                float xx2 = fminf(boxes[i][2], boxes[j][2]);
                float yy2 = fminf(boxes[i][3], boxes[j][3]);
                float inter = fmaxf(xx2 - xx1, 0.f) * fmaxf(yy2 - yy1, 0.f);
                float iou = inter / (area[i] + area[j] - inter);
                if (iou > 0.5f) supp[j] = true;
            }
        }
        for (int k = 0; k < NTOP; k++)
            out[OFF_KEEP + b * NTOP + k] = supp[k] ? 0.f : 1.f;
    }
}

// ---------------- launch -----------------------------------------------------
extern "C" void kernel_launch(void* const* d_in, const int* in_sizes, int n_in,
                              void* d_out, int out_size)
{
    const float* memory        = (const float*)d_in[0];
    const unsigned char* mask  = (const unsigned char*)d_in[1];
    const float* WH            = (const float*)d_in[2];
    const float* W_enc         = (const float*)d_in[3];
    const float* b_enc         = (const float*)d_in[4];
    const float* ln_g          = (const float*)d_in[5];
    const float* ln_b          = (const float*)d_in[6];
    const float* W_cls         = (const float*)d_in[7];
    const float* b_cls         = (const float*)d_in[8];
    const float* W1            = (const float*)d_in[9];
    const float* b1            = (const float*)d_in[10];
    const float* W2            = (const float*)d_in[11];
    const float* b2            = (const float*)d_in[12];
    const float* W3            = (const float*)d_in[13];
    const float* b3            = (const float*)d_in[14];
    float* out = (float*)d_out;

    float *p_tmp, *p_outmem, *p_logits, *p_scores, *p_scratch, *p_topsc, *p_ctop;
    unsigned char* p_rowinv; int* p_topidx;
    cudaGetSymbolAddress((void**)&p_tmp,     g_tmp);
    cudaGetSymbolAddress((void**)&p_outmem,  g_outmem);
    cudaGetSymbolAddress((void**)&p_logits,  g_logits);
    cudaGetSymbolAddress((void**)&p_scores,  g_scores);
    cudaGetSymbolAddress((void**)&p_scratch, g_scratch);
    cudaGetSymbolAddress((void**)&p_rowinv,  g_rowinv);
    cudaGetSymbolAddress((void**)&p_topidx,  g_topidx);
    cudaGetSymbolAddress((void**)&p_topsc,   g_topsc);
    cudaGetSymbolAddress((void**)&p_ctop,    g_ctop);

    props_kernel<<<(MROWS + 255) / 256, 256>>>(mask, p_rowinv);

    dim3 gFull((MROWS + 127) / 128, 2);
    dim3 gCls((MROWS + 127) / 128, 1);
    // tmp = mem_masked @ W_enc + b_enc
    sgemm2_kernel<<<gFull, 256>>>(memory, W_enc, b_enc, p_tmp, MROWS, CH, 0, p_rowinv, nullptr);
    // out_mem = LN(tmp)*g + b
    ln_kernel<<<MROWS / 8, 256>>>(p_tmp, ln_g, ln_b, p_outmem);
    // logits = out_mem @ W_cls + b_cls, fused row-max -> scores
    sgemm2_kernel<<<gCls, 256>>>(p_outmem, W_cls, b_cls, p_logits, MROWS, NC, 0, nullptr, p_scores);
    // top-20 per batch
    topk_kernel<<<BSZ, 1024>>>(p_scores, p_scratch, p_topidx, p_topsc);
    // MLP + coords only on the 160 selected rows
    tinymlp_kernel<<<BSZ * NTOP, 256>>>(p_outmem, mask, W1, b1, W2, b2, W3, b3,
                                        p_topidx, p_ctop);
    // gather + sigmoid + NMS + writes
    final_kernel<<<BSZ, 128>>>(p_logits, p_ctop, p_topidx, p_topsc, WH, out);

    (void)in_sizes; (void)n_in; (void)out_size;
}

// round 13
// speedup vs baseline: 3.5439x; 1.1427x over previous
#include <cuda_runtime.h>
#include <math.h>
#include <stdint.h>
#include <string.h>

#define BSZ   8
#define SEQ   19947
#define MROWS 159576          // BSZ*SEQ
#define CH    256
#define NC    91
#define NTOP  20
#define CHUNKS 16
#define CHUNK  1247           // ceil(SEQ/16); last chunk = 1242

// output layout (float32, concatenated flattened tuple)
#define OFF_OUT  0            // (8,20,95)
#define OFF_REF  15200        // (8,20,4)
#define OFF_KEEP 15840        // (8,20)
#define OFF_SC   16000        // (8,20)

// ---------------- scratch (device globals: allocation-free) ----------------
__device__ float g_outmem[MROWS * CH];
__device__ float g_logits[MROWS * NC];
__device__ float g_scores[MROWS];
__device__ int   g_topidx[BSZ * NTOP];
__device__ float g_topsc[BSZ * NTOP];
__device__ float g_ctop[BSZ * NTOP * 4];
__device__ float g_candV[BSZ * CHUNKS * NTOP];
__device__ int   g_candI[BSZ * CHUNKS * NTOP];

// ---------------- packed f32x2 helpers (Blackwell FFMA2) -------------------
__device__ __forceinline__ unsigned long long ffma2(unsigned long long a,
                                                    unsigned long long b,
                                                    unsigned long long c)
{
    unsigned long long d;
    asm("fma.rn.f32x2 %0, %1, %2, %3;" : "=l"(d) : "l"(a), "l"(b), "l"(c));
    return d;
}
__device__ __forceinline__ unsigned long long bcast2(float x)
{
    unsigned long long d;
    unsigned int xi = __float_as_uint(x);
    asm("mov.b64 %0, {%1, %1};" : "=l"(d) : "r"(xi));
    return d;
}
__device__ __forceinline__ float pickhalf(unsigned long long v, int half)
{
    float2 p;
    memcpy(&p, &v, 8);
    return half ? p.y : p.x;
}

// row validity by geometry + mask (reference _gen_proposals semantics)
__device__ __forceinline__ bool row_valid_geom(int s)
{
    int Hh, Ww, t;
    if (s < 15000)      { Hh = 100; Ww = 150; t = s; }
    else if (s < 18750) { Hh = 50;  Ww = 75;  t = s - 15000; }
    else if (s < 19700) { Hh = 25;  Ww = 38;  t = s - 18750; }
    else                { Hh = 13;  Ww = 19;  t = s - 19700; }
    int y = t / Ww, x = t % Ww;
    float cx = ((float)x + 0.5f) / (float)Ww;
    float cy = ((float)y + 0.5f) / (float)Hh;
    return (cx > 0.01f) && (cx < 0.99f) && (cy > 0.01f) && (cy < 0.99f);
}

// ============ GEMM1 + bias + LayerNorm fused =================================
// out_mem[M,256] = LN(mem_masked @ W_enc + b_enc) * g + b
// 512 threads, tile 128x256, 8x8 microtile packed f32x2.
// dynamic smem: As 2*16*132 | Bs 2*16*256 | red 4*128   (floats)
#define GL_AS 0
#define GL_BS (2 * 16 * 132)
#define GL_RED (GL_BS + 2 * 16 * 256)
#define GL_SMEM_BYTES ((GL_RED + 4 * 128) * 4)

__global__ void __launch_bounds__(512, 1)
gemm_ln_kernel(const float* __restrict__ A, const unsigned char* __restrict__ mask,
               const float* __restrict__ Bm, const float* __restrict__ bias,
               const float* __restrict__ lng, const float* __restrict__ lnb,
               float* __restrict__ Y)
{
    extern __shared__ float smf[];
    float* AsB = smf + GL_AS;     // [buf][16][132]
    float* BsB = smf + GL_BS;     // [buf][16][256]
    float* red = smf + GL_RED;    // [4][128]

    const int tid = threadIdx.x;
    const int warp = tid >> 5, lane = tid & 31;
    const int rowBase = blockIdx.x * 128;

    const int tRow = (warp & 3) * 32 + (lane & 3) * 8;
    const int tCol = (warp >> 2) * 64 + (lane >> 2) * 8;
    const int wcg  = warp >> 2;

    // A loader: one row per 4 threads
    const int aRow = tid >> 2, aK = (tid & 3) << 2;
    const int agr = rowBase + aRow;
    bool avalid = false;
    if (agr < MROWS) {
        int s = agr % SEQ;
        avalid = (mask[agr] == 0) && row_valid_geom(s);
    }
    const float* arow = A + (size_t)agr * CH;
    // B loader: 2 float4 per thread
    const int bK0 = tid >> 6, bN = (tid & 63) << 2, bK1 = bK0 + 8;

    unsigned long long acc2[4][8];
#pragma unroll
    for (int r = 0; r < 4; r++)
#pragma unroll
        for (int c = 0; c < 8; c++) acc2[r][c] = 0ull;

    float4 a0r = avalid ? *reinterpret_cast<const float4*>(arow + aK)
                        : make_float4(0.f, 0.f, 0.f, 0.f);
    float4 b0r = *reinterpret_cast<const float4*>(Bm + (size_t)bK0 * CH + bN);
    float4 b1r = *reinterpret_cast<const float4*>(Bm + (size_t)bK1 * CH + bN);
    AsB[(aK+0)*132 + aRow] = a0r.x; AsB[(aK+1)*132 + aRow] = a0r.y;
    AsB[(aK+2)*132 + aRow] = a0r.z; AsB[(aK+3)*132 + aRow] = a0r.w;
    *reinterpret_cast<float4*>(&BsB[bK0*256 + bN]) = b0r;
    *reinterpret_cast<float4*>(&BsB[bK1*256 + bN]) = b1r;
    __syncthreads();

#pragma unroll 1
    for (int kb = 0; kb < 16; kb++) {
        const int cur = kb & 1;
        float* As = AsB + cur * (16 * 132);
        float* Bs = BsB + cur * (16 * 256);
        if (kb < 15) {
            int k0 = (kb + 1) * 16;
            a0r = avalid ? *reinterpret_cast<const float4*>(arow + k0 + aK)
                         : make_float4(0.f, 0.f, 0.f, 0.f);
            b0r = *reinterpret_cast<const float4*>(Bm + (size_t)(k0 + bK0) * CH + bN);
            b1r = *reinterpret_cast<const float4*>(Bm + (size_t)(k0 + bK1) * CH + bN);
        }
#pragma unroll
        for (int kk = 0; kk < 16; kk++) {
            ulonglong2 a01 = *reinterpret_cast<const ulonglong2*>(&As[kk*132 + tRow]);
            ulonglong2 a23 = *reinterpret_cast<const ulonglong2*>(&As[kk*132 + tRow + 4]);
            float4 b0 = *reinterpret_cast<const float4*>(&Bs[kk*256 + tCol]);
            float4 b1 = *reinterpret_cast<const float4*>(&Bs[kk*256 + tCol + 4]);
            unsigned long long av[4] = {a01.x, a01.y, a23.x, a23.y};
            float bf[8] = {b0.x, b0.y, b0.z, b0.w, b1.x, b1.y, b1.z, b1.w};
#pragma unroll
            for (int c = 0; c < 8; c++) {
                unsigned long long bc = bcast2(bf[c]);
#pragma unroll
                for (int r = 0; r < 4; r++)
                    acc2[r][c] = ffma2(av[r], bc, acc2[r][c]);
            }
        }
        if (kb < 15) {
            float* Asn = AsB + (cur ^ 1) * (16 * 132);
            float* Bsn = BsB + (cur ^ 1) * (16 * 256);
            Asn[(aK+0)*132 + aRow] = a0r.x; Asn[(aK+1)*132 + aRow] = a0r.y;
            Asn[(aK+2)*132 + aRow] = a0r.z; Asn[(aK+3)*132 + aRow] = a0r.w;
            *reinterpret_cast<float4*>(&Bsn[bK0*256 + bN]) = b0r;
            *reinterpret_cast<float4*>(&Bsn[bK1*256 + bN]) = b1r;
            __syncthreads();
        }
    }

    // ---- epilogue: bias + LayerNorm ----
    float4 bb0 = *reinterpret_cast<const float4*>(&bias[tCol]);
    float4 bb1 = *reinterpret_cast<const float4*>(&bias[tCol + 4]);
    float bcol[8] = {bb0.x, bb0.y, bb0.z, bb0.w, bb1.x, bb1.y, bb1.z, bb1.w};

    // pass 1: row sums -> mean
    float mrow[4][2];
#pragma unroll
    for (int r2 = 0; r2 < 4; r2++)
#pragma unroll
        for (int half = 0; half < 2; half++) {
            float ps = 0.f;
#pragma unroll
            for (int c = 0; c < 8; c++) ps += pickhalf(acc2[r2][c], half) + bcol[c];
#pragma unroll
            for (int off = 4; off <= 16; off <<= 1)
                ps += __shfl_xor_sync(0xffffffffu, ps, off);
            if ((lane >> 2) == 0)
                red[wcg * 128 + tRow + 2 * r2 + half] = ps;
            mrow[r2][half] = 0.f;
        }
    __syncthreads();
#pragma unroll
    for (int r2 = 0; r2 < 4; r2++)
#pragma unroll
        for (int half = 0; half < 2; half++) {
            int lr = tRow + 2 * r2 + half;
            mrow[r2][half] = (red[lr] + red[128 + lr] + red[256 + lr] + red[384 + lr])
                             * (1.f / 256.f);
        }
    __syncthreads();
    // pass 2: sum (x-m)^2 -> var
    float vrow[4][2];
#pragma unroll
    for (int r2 = 0; r2 < 4; r2++)
#pragma unroll
        for (int half = 0; half < 2; half++) {
            float m = mrow[r2][half];
            float ps = 0.f;
#pragma unroll
            for (int c = 0; c < 8; c++) {
                float d = pickhalf(acc2[r2][c], half) + bcol[c] - m;
                ps = fmaf(d, d, ps);
            }
#pragma unroll
            for (int off = 4; off <= 16; off <<= 1)
                ps += __shfl_xor_sync(0xffffffffu, ps, off);
            if ((lane >> 2) == 0)
                red[wcg * 128 + tRow + 2 * r2 + half] = ps;
            vrow[r2][half] = 0.f;
        }
    __syncthreads();
#pragma unroll
    for (int r2 = 0; r2 < 4; r2++)
#pragma unroll
        for (int half = 0; half < 2; half++) {
            int lr = tRow + 2 * r2 + half;
            vrow[r2][half] = (red[lr] + red[128 + lr] + red[256 + lr] + red[384 + lr])
                             * (1.f / 256.f);
        }

    float4 gg0 = *reinterpret_cast<const float4*>(&lng[tCol]);
    float4 gg1 = *reinterpret_cast<const float4*>(&lng[tCol + 4]);
    float4 ob0 = *reinterpret_cast<const float4*>(&lnb[tCol]);
    float4 ob1 = *reinterpret_cast<const float4*>(&lnb[tCol + 4]);
    float gcol[8] = {gg0.x, gg0.y, gg0.z, gg0.w, gg1.x, gg1.y, gg1.z, gg1.w};
    float ocol[8] = {ob0.x, ob0.y, ob0.z, ob0.w, ob1.x, ob1.y, ob1.z, ob1.w};

#pragma unroll
    for (int r2 = 0; r2 < 4; r2++)
#pragma unroll
        for (int half = 0; half < 2; half++) {
            int gr = rowBase + tRow + 2 * r2 + half;
            if (gr >= MROWS) continue;
            float m = mrow[r2][half];
            float inv = 1.f / sqrtf(vrow[r2][half] + 1e-5f);
            float o[8];
#pragma unroll
            for (int c = 0; c < 8; c++) {
                float x = pickhalf(acc2[r2][c], half) + bcol[c];
                o[c] = (x - m) * inv * gcol[c] + ocol[c];
            }
            float4 v0 = make_float4(o[0], o[1], o[2], o[3]);
            float4 v1 = make_float4(o[4], o[5], o[6], o[7]);
            *reinterpret_cast<float4*>(&Y[(size_t)gr * CH + tCol]) = v0;
            *reinterpret_cast<float4*>(&Y[(size_t)gr * CH + tCol + 4]) = v1;
        }
}

// ============ cls GEMM: logits = out_mem @ W_cls + b_cls, fused row-max =====
// 256 threads, tile 128x96 (N=91 padded to 96), 8x6 microtile.
__global__ void __launch_bounds__(256, 2)
cls_kernel(const float* __restrict__ A, const float* __restrict__ W,
           const float* __restrict__ bias, float* __restrict__ C,
           float* __restrict__ scores)
{
    __shared__ float As[2][16][132];
    __shared__ float Bs[2][16][96];

    const int tid = threadIdx.x;
    const int warp = tid >> 5, lane = tid & 31;
    const int rowBase = blockIdx.x * 128;

    const int tRow = (warp & 3) * 32 + (lane & 3) * 8;
    const int tCol = (warp >> 2) * 48 + (lane >> 2) * 6;

    const int aRow0 = tid >> 2, aK = (tid & 3) << 2, aRow1 = aRow0 + 64;
    const int bKf = tid >> 4, bNf = (tid & 15) * 6;

    unsigned long long acc2[4][6];
#pragma unroll
    for (int r = 0; r < 4; r++)
#pragma unroll
        for (int c = 0; c < 6; c++) acc2[r][c] = 0ull;

    auto loadArow = [&](int gr, int kOff) {
        if (gr < MROWS)
            return *reinterpret_cast<const float4*>(A + (size_t)gr * CH + kOff);
        return make_float4(0.f, 0.f, 0.f, 0.f);
    };
    auto fillB = [&](int kb, int buf) {
        int gk = kb * 16 + bKf;
#pragma unroll
        for (int j = 0; j < 6; j++) {
            int n = bNf + j;
            Bs[buf][bKf][n] = (n < NC) ? W[(size_t)gk * NC + n] : 0.f;
        }
    };

    float4 a0r = loadArow(rowBase + aRow0, aK);
    float4 a1r = loadArow(rowBase + aRow1, aK);
    As[0][aK+0][aRow0] = a0r.x; As[0][aK+1][aRow0] = a0r.y;
    As[0][aK+2][aRow0] = a0r.z; As[0][aK+3][aRow0] = a0r.w;
    As[0][aK+0][aRow1] = a1r.x; As[0][aK+1][aRow1] = a1r.y;
    As[0][aK+2][aRow1] = a1r.z; As[0][aK+3][aRow1] = a1r.w;
    fillB(0, 0);
    __syncthreads();

#pragma unroll 1
    for (int kb = 0; kb < 16; kb++) {
        const int cur = kb & 1;
        if (kb < 15) {
            a0r = loadArow(rowBase + aRow0, (kb + 1) * 16 + aK);
            a1r = loadArow(rowBase + aRow1, (kb + 1) * 16 + aK);
        }
#pragma unroll
        for (int kk = 0; kk < 16; kk++) {
            ulonglong2 a01 = *reinterpret_cast<const ulonglong2*>(&As[cur][kk][tRow]);
            ulonglong2 a23 = *reinterpret_cast<const ulonglong2*>(&As[cur][kk][tRow + 4]);
            float2 b01 = *reinterpret_cast<const float2*>(&Bs[cur][kk][tCol]);
            float2 b23 = *reinterpret_cast<const float2*>(&Bs[cur][kk][tCol + 2]);
            float2 b45 = *reinterpret_cast<const float2*>(&Bs[cur][kk][tCol + 4]);
            unsigned long long av[4] = {a01.x, a01.y, a23.x, a23.y};
            float bf[6] = {b01.x, b01.y, b23.x, b23.y, b45.x, b45.y};
#pragma unroll
            for (int c = 0; c < 6; c++) {
                unsigned long long bc = bcast2(bf[c]);
#pragma unroll
                for (int r = 0; r < 4; r++)
                    acc2[r][c] = ffma2(av[r], bc, acc2[r][c]);
            }
        }
        if (kb < 15) {
            const int nxt = 1 - cur;
            As[nxt][aK+0][aRow0] = a0r.x; As[nxt][aK+1][aRow0] = a0r.y;
            As[nxt][aK+2][aRow0] = a0r.z; As[nxt][aK+3][aRow0] = a0r.w;
            As[nxt][aK+0][aRow1] = a1r.x; As[nxt][aK+1][aRow1] = a1r.y;
            As[nxt][aK+2][aRow1] = a1r.z; As[nxt][aK+3][aRow1] = a1r.w;
            fillB(kb + 1, nxt);
            __syncthreads();
        }
    }

    // ---- epilogue: store logits (gc<91) + fused row-max ----
    float rmaxv[4][2];
#pragma unroll
    for (int r2 = 0; r2 < 4; r2++)
#pragma unroll
        for (int half = 0; half < 2; half++) {
            int gr = rowBase + tRow + 2 * r2 + half;
            float m = -INFINITY;
#pragma unroll
            for (int c = 0; c < 6; c++) {
                int gc = tCol + c;
                if (gc < NC) {
                    float v = pickhalf(acc2[r2][c], half) + bias[gc];
                    if (gr < MROWS) C[(size_t)gr * NC + gc] = v;
                    m = fmaxf(m, v);
                }
            }
            rmaxv[r2][half] = m;
        }
    __syncthreads();                      // all warps done reading As
    float* red = &As[0][0][0];            // reuse as [128][16]
    int slot = ((warp >> 2) << 3) | (lane >> 2);
#pragma unroll
    for (int r2 = 0; r2 < 4; r2++)
#pragma unroll
        for (int half = 0; half < 2; half++)
            red[(tRow + 2 * r2 + half) * 16 + slot] = rmaxv[r2][half];
    __syncthreads();
    if (tid < 128) {
        int gr = rowBase + tid;
        if (gr < MROWS) {
            float m = -INFINITY;
#pragma unroll
            for (int s = 0; s < 16; s++) m = fmaxf(m, red[tid * 16 + s]);
            scores[gr] = m;
        }
    }
}

// ============ top-k, two phase ==============================================
__global__ void topk1_kernel(const float* __restrict__ scores,
                             float* __restrict__ candV, int* __restrict__ candI)
{
    const int c = blockIdx.x, b = blockIdx.y;
    const int base = c * CHUNK;
    const int cnt = min(CHUNK, SEQ - base);
    __shared__ float vals[CHUNK];
    __shared__ float wv[8];
    __shared__ int   wi[8];
    const int tid = threadIdx.x, lane = tid & 31, warp = tid >> 5;

    for (int i = tid; i < cnt; i += 256) vals[i] = scores[(size_t)b * SEQ + base + i];
    __syncthreads();

    for (int it = 0; it < NTOP; it++) {
        float bv = -INFINITY; int bi = 0x7fffffff;
        for (int i = tid; i < cnt; i += 256) {
            float v = vals[i];
            if (v > bv || (v == bv && i < bi)) { bv = v; bi = i; }
        }
#pragma unroll
        for (int off = 16; off; off >>= 1) {
            float ov = __shfl_xor_sync(0xffffffffu, bv, off);
            int   oi = __shfl_xor_sync(0xffffffffu, bi, off);
            if (ov > bv || (ov == bv && oi < bi)) { bv = ov; bi = oi; }
        }
        if (lane == 0) { wv[warp] = bv; wi[warp] = bi; }
        __syncthreads();
        if (tid == 0) {
            float fv = wv[0]; int fi = wi[0];
#pragma unroll
            for (int w = 1; w < 8; w++)
                if (wv[w] > fv || (wv[w] == fv && wi[w] < fi)) { fv = wv[w]; fi = wi[w]; }
            int o = (b * CHUNKS + c) * NTOP + it;
            candV[o] = fv; candI[o] = base + fi;
            vals[fi] = -INFINITY;
        }
        __syncthreads();
    }
}

__global__ void topk2_kernel(const float* __restrict__ candV, const int* __restrict__ candI,
                             int* __restrict__ topIdx, float* __restrict__ topSc)
{
    const int b = blockIdx.x;
    const int NCAND = CHUNKS * NTOP;       // 320
    __shared__ float cv[NCAND];
    __shared__ int   ci[NCAND];
    __shared__ float wv[10];
    __shared__ int   wgi[10], wps[10];
    const int tid = threadIdx.x, lane = tid & 31, warp = tid >> 5;

    if (tid < NCAND) { cv[tid] = candV[b * NCAND + tid]; ci[tid] = candI[b * NCAND + tid]; }
    __syncthreads();

    for (int it = 0; it < NTOP; it++) {
        float v = (tid < NCAND) ? cv[tid] : -INFINITY;
        int gi = (tid < NCAND) ? ci[tid] : 0x7fffffff;
        int ps = tid;
#pragma unroll
        for (int off = 16; off; off >>= 1) {
            float ov = __shfl_xor_sync(0xffffffffu, v, off);
            int  ogi = __shfl_xor_sync(0xffffffffu, gi, off);
            int  ops = __shfl_xor_sync(0xffffffffu, ps, off);
            if (ov > v || (ov == v && ogi < gi)) { v = ov; gi = ogi; ps = ops; }
        }
        if (lane == 0) { wv[warp] = v; wgi[warp] = gi; wps[warp] = ps; }
        __syncthreads();
        if (tid == 0) {
            float fv = wv[0]; int fgi = wgi[0], fps = wps[0];
#pragma unroll
            for (int w = 1; w < 10; w++)
                if (wv[w] > fv || (wv[w] == fv && wgi[w] < fgi)) {
                    fv = wv[w]; fgi = wgi[w]; fps = wps[w];
                }
            topIdx[b * NTOP + it] = fgi;
            topSc[b * NTOP + it]  = fv;
            cv[fps] = -INFINITY;
        }
        __syncthreads();
    }
}

// ---------------- tiny MLP on top-k rows only --------------------------------
__global__ void tinymlp_kernel(const float* __restrict__ outmem,
                               const unsigned char* __restrict__ mask,
                               const float* __restrict__ W1, const float* __restrict__ b1,
                               const float* __restrict__ W2, const float* __restrict__ b2,
                               const float* __restrict__ W3, const float* __restrict__ b3,
                               const int* __restrict__ topIdx,
                               float* __restrict__ coordsTop)
{
    __shared__ float s0[256], s1[256];
    const int blk = blockIdx.x;               // 0..159
    const int b = blk / NTOP;
    const int s = topIdx[blk];                // within-batch index
    const size_t row = (size_t)b * SEQ + s;
    const int tid = threadIdx.x;

    s0[tid] = outmem[row * CH + tid];
    __syncthreads();

    float acc = 0.f;
#pragma unroll 8
    for (int kk = 0; kk < CH; kk++) acc = fmaf(s0[kk], W1[kk * CH + tid], acc);
    s1[tid] = fmaxf(acc + b1[tid], 0.f);
    __syncthreads();

    acc = 0.f;
#pragma unroll 8
    for (int kk = 0; kk < CH; kk++) acc = fmaf(s1[kk], W2[kk * CH + tid], acc);
    float h2 = fmaxf(acc + b2[tid], 0.f);
    __syncthreads();
    s0[tid] = h2;
    __syncthreads();

    const int warp = tid >> 5, lane = tid & 31;
    if (warp < 4) {
        float a = 0.f;
        for (int kk = lane; kk < CH; kk += 32)
            a = fmaf(s0[kk], W3[kk * 4 + warp], a);
#pragma unroll
        for (int off = 16; off; off >>= 1) a += __shfl_xor_sync(0xffffffffu, a, off);
        if (lane == 0) {
            int Hh, Ww, t;
            if (s < 15000)      { Hh = 100; Ww = 150; t = s; }
            else if (s < 18750) { Hh = 50;  Ww = 75;  t = s - 15000; }
            else if (s < 19700) { Hh = 25;  Ww = 38;  t = s - 18750; }
            else                { Hh = 13;  Ww = 19;  t = s - 19700; }
            int lvl = (s < 15000) ? 0 : (s < 18750) ? 1 : (s < 19700) ? 2 : 3;
            int y = t / Ww, x = t % Ww;
            float cx = ((float)x + 0.5f) / (float)Ww;
            float cy = ((float)y + 0.5f) / (float)Hh;
            float wh = 0.05f * (float)(1 << lvl);
            bool valid = (cx > 0.01f) && (cx < 0.99f) &&
                         (cy > 0.01f) && (cy < 0.99f);
            bool inv = (mask[row] != 0) || !valid;
            float pv;
            if (inv) pv = INFINITY;
            else {
                float comp = (warp == 0) ? cx : (warp == 1) ? cy : wh;
                pv = logf(comp / (1.f - comp));
            }
            coordsTop[blk * 4 + warp] = a + b3[warp] + pv;
        }
    }
}

// ---------------- final: gather + sigmoid + boxes + NMS ----------------------
__global__ void final_kernel(const float* __restrict__ logits,
                             const float* __restrict__ coordsTop,
                             const int* __restrict__ topIdx, const float* __restrict__ topSc,
                             const float* __restrict__ WH, float* __restrict__ out)
{
    int b = blockIdx.x, tid = threadIdx.x;
    __shared__ int   idxs[NTOP];
    __shared__ float refp[NTOP][4];
    __shared__ float boxes[NTOP][4];
    if (tid < NTOP) idxs[tid] = topIdx[b * NTOP + tid];
    __syncthreads();

    for (int o = tid; o < NTOP * NC; o += blockDim.x) {
        int k = o / NC, c = o % NC;
        size_t row = (size_t)b * SEQ + idxs[k];
        out[OFF_OUT + b * (NTOP * (NC + 4)) + k * (NC + 4) + c] = logits[row * NC + c];
    }
    if (tid < NTOP * 4) {
        int k = tid >> 2, c = tid & 3;
        float v = coordsTop[(b * NTOP + k) * 4 + c];
        out[OFF_OUT + b * (NTOP * (NC + 4)) + k * (NC + 4) + NC + c] = v;
        float r = 1.f / (1.f + expf(-v));
        out[OFF_REF + b * (NTOP * 4) + k * 4 + c] = r;
        refp[k][c] = r;
    }
    if (tid < NTOP) out[OFF_SC + b * NTOP + tid] = topSc[b * NTOP + tid];
    __syncthreads();
    if (tid < NTOP) {
        float cx = refp[tid][0], cy = refp[tid][1], w = refp[tid][2], h = refp[tid][3];
        boxes[tid][0] = truncf((cx - 0.5f * w) * WH[b * 4 + 0]);
        boxes[tid][1] = truncf((cy - 0.5f * h) * WH[b * 4 + 1]);
        boxes[tid][2] = truncf((cx + 0.5f * w) * WH[b * 4 + 2]);
        boxes[tid][3] = truncf((cy + 0.5f * h) * WH[b * 4 + 3]);
    }
    __syncthreads();
    if (tid == 0) {
        bool supp[NTOP];
        float area[NTOP];
        for (int k = 0; k < NTOP; k++) {
            supp[k] = false;
            area[k] = (boxes[k][2] - boxes[k][0]) * (boxes[k][3] - boxes[k][1]);
        }
        for (int i = 0; i < NTOP; i++) {
            if (supp[i]) continue;
            for (int j = i + 1; j < NTOP; j++) {
                float xx1 = fmaxf(boxes[i][0], boxes[j][0]);
                float yy1 = fmaxf(boxes[i][1], boxes[j][1]);
                float xx2 = fminf(boxes[i][2], boxes[j][2]);
                float yy2 = fminf(boxes[i][3], boxes[j][3]);
                float inter = fmaxf(xx2 - xx1, 0.f) * fmaxf(yy2 - yy1, 0.f);
                float iou = inter / (area[i] + area[j] - inter);
                if (iou > 0.5f) supp[j] = true;
            }
        }
        for (int k = 0; k < NTOP; k++)
            out[OFF_KEEP + b * NTOP + k] = supp[k] ? 0.f : 1.f;
    }
}

// ---------------- launch -----------------------------------------------------
extern "C" void kernel_launch(void* const* d_in, const int* in_sizes, int n_in,
                              void* d_out, int out_size)
{
    const float* memory        = (const float*)d_in[0];
    const unsigned char* mask  = (const unsigned char*)d_in[1];
    const float* WH            = (const float*)d_in[2];
    const float* W_enc         = (const float*)d_in[3];
    const float* b_enc         = (const float*)d_in[4];
    const float* ln_g          = (const float*)d_in[5];
    const float* ln_b          = (const float*)d_in[6];
    const float* W_cls         = (const float*)d_in[7];
    const float* b_cls         = (const float*)d_in[8];
    const float* W1            = (const float*)d_in[9];
    const float* b1            = (const float*)d_in[10];
    const float* W2            = (const float*)d_in[11];
    const float* b2            = (const float*)d_in[12];
    const float* W3            = (const float*)d_in[13];
    const float* b3            = (const float*)d_in[14];
    float* out = (float*)d_out;

    float *p_outmem, *p_logits, *p_scores, *p_topsc, *p_ctop, *p_candV;
    int *p_topidx, *p_candI;
    cudaGetSymbolAddress((void**)&p_outmem,  g_outmem);
    cudaGetSymbolAddress((void**)&p_logits,  g_logits);
    cudaGetSymbolAddress((void**)&p_scores,  g_scores);
    cudaGetSymbolAddress((void**)&p_topidx,  g_topidx);
    cudaGetSymbolAddress((void**)&p_topsc,   g_topsc);
    cudaGetSymbolAddress((void**)&p_ctop,    g_ctop);
    cudaGetSymbolAddress((void**)&p_candV,   g_candV);
    cudaGetSymbolAddress((void**)&p_candI,   g_candI);

    cudaFuncSetAttribute(gemm_ln_kernel,
                         cudaFuncAttributeMaxDynamicSharedMemorySize, GL_SMEM_BYTES);

    const int gRows = (MROWS + 127) / 128;   // 1247
    // out_mem = LN(mem_masked @ W_enc + b_enc)
    gemm_ln_kernel<<<gRows, 512, GL_SMEM_BYTES>>>(memory, mask, W_enc, b_enc,
                                                  ln_g, ln_b, p_outmem);
    // logits = out_mem @ W_cls + b_cls, fused row-max -> scores
    cls_kernel<<<gRows, 256>>>(p_outmem, W_cls, b_cls, p_logits, p_scores);
    // top-20 per batch (two-phase)
    topk1_kernel<<<dim3(CHUNKS, BSZ), 256>>>(p_scores, p_candV, p_candI);
    topk2_kernel<<<BSZ, 320>>>(p_candV, p_candI, p_topidx, p_topsc);
    // MLP + coords only on the 160 selected rows
    tinymlp_kernel<<<BSZ * NTOP, 256>>>(p_outmem, mask, W1, b1, W2, b2, W3, b3,
                                        p_topidx, p_ctop);
    // gather + sigmoid + NMS + writes
    final_kernel<<<BSZ, 128>>>(p_logits, p_ctop, p_topidx, p_topsc, WH, out);

    (void)in_sizes; (void)n_in; (void)out_size;
}

// round 14
// speedup vs baseline: 3.5584x; 1.0041x over previous
#include <cuda_runtime.h>
#include <math.h>
#include <stdint.h>
#include <string.h>

#define BSZ   8
#define SEQ   19947
#define MROWS 159576          // BSZ*SEQ
#define CH    256
#define NC    91
#define NCP   96              // padded cls width
#define NTOP  20
#define CHUNKS 16
#define CHUNK  1247           // ceil(SEQ/16); last chunk = 1242

// output layout (float32, concatenated flattened tuple)
#define OFF_OUT  0            // (8,20,95)
#define OFF_REF  15200        // (8,20,4)
#define OFF_KEEP 15840        // (8,20)
#define OFF_SC   16000        // (8,20)

// ---------------- scratch (device globals: allocation-free) ----------------
__device__ float g_outmem[MROWS * CH];
__device__ float g_logits[MROWS * NC];
__device__ float g_scores[MROWS];
__device__ int   g_topidx[BSZ * NTOP];
__device__ float g_topsc[BSZ * NTOP];
__device__ float g_ctop[BSZ * NTOP * 4];
__device__ float g_candV[BSZ * CHUNKS * NTOP];
__device__ int   g_candI[BSZ * CHUNKS * NTOP];
__device__ float g_wpad[CH * NCP];        // W_cls padded to [256][96]

// ---------------- packed f32x2 helpers (Blackwell FFMA2) -------------------
__device__ __forceinline__ unsigned long long ffma2(unsigned long long a,
                                                    unsigned long long b,
                                                    unsigned long long c)
{
    unsigned long long d;
    asm("fma.rn.f32x2 %0, %1, %2, %3;" : "=l"(d) : "l"(a), "l"(b), "l"(c));
    return d;
}
__device__ __forceinline__ unsigned long long bcast2(float x)
{
    unsigned long long d;
    unsigned int xi = __float_as_uint(x);
    asm("mov.b64 %0, {%1, %1};" : "=l"(d) : "r"(xi));
    return d;
}
__device__ __forceinline__ float pickhalf(unsigned long long v, int half)
{
    float2 p;
    memcpy(&p, &v, 8);
    return half ? p.y : p.x;
}

// row validity by geometry + mask (reference _gen_proposals semantics)
__device__ __forceinline__ bool row_valid_geom(int s)
{
    int Hh, Ww, t;
    if (s < 15000)      { Hh = 100; Ww = 150; t = s; }
    else if (s < 18750) { Hh = 50;  Ww = 75;  t = s - 15000; }
    else if (s < 19700) { Hh = 25;  Ww = 38;  t = s - 18750; }
    else                { Hh = 13;  Ww = 19;  t = s - 19700; }
    int y = t / Ww, x = t % Ww;
    float cx = ((float)x + 0.5f) / (float)Ww;
    float cy = ((float)y + 0.5f) / (float)Hh;
    return (cx > 0.01f) && (cx < 0.99f) && (cy > 0.01f) && (cy < 0.99f);
}

// ---------------- pad W_cls [256][91] -> [256][96] ---------------------------
__global__ void wpad_kernel(const float* __restrict__ Wc, float* __restrict__ Wp)
{
    int idx = blockIdx.x * 256 + threadIdx.x;
    if (idx >= CH * NCP) return;
    int k = idx / NCP, n = idx % NCP;
    Wp[idx] = (n < NC) ? Wc[k * NC + n] : 0.f;
}

// ============ GEMM1 + bias + LayerNorm fused =================================
// out_mem[M,256] = LN(mem_masked @ W_enc + b_enc) * g + b
// 512 threads, tile 128x256, 8x8 microtile packed f32x2.
#define GL_AS 0
#define GL_BS (2 * 16 * 132)
#define GL_RED (GL_BS + 2 * 16 * 256)
#define GL_SMEM_BYTES ((GL_RED + 4 * 128) * 4)

__global__ void __launch_bounds__(512, 1)
gemm_ln_kernel(const float* __restrict__ A, const unsigned char* __restrict__ mask,
               const float* __restrict__ Bm, const float* __restrict__ bias,
               const float* __restrict__ lng, const float* __restrict__ lnb,
               float* __restrict__ Y)
{
    extern __shared__ float smf[];
    float* AsB = smf + GL_AS;     // [buf][16][132]
    float* BsB = smf + GL_BS;     // [buf][16][256]
    float* red = smf + GL_RED;    // [4][128]

    const int tid = threadIdx.x;
    const int warp = tid >> 5, lane = tid & 31;
    const int rowBase = blockIdx.x * 128;

    const int tRow = (warp & 3) * 32 + (lane & 3) * 8;
    const int tCol = (warp >> 2) * 64 + (lane >> 2) * 8;
    const int wcg  = warp >> 2;

    const int aRow = tid >> 2, aK = (tid & 3) << 2;
    const int agr = rowBase + aRow;
    bool avalid = false;
    if (agr < MROWS) {
        int s = agr % SEQ;
        avalid = (mask[agr] == 0) && row_valid_geom(s);
    }
    const float* arow = A + (size_t)agr * CH;
    const int bK0 = tid >> 6, bN = (tid & 63) << 2, bK1 = bK0 + 8;

    unsigned long long acc2[4][8];
#pragma unroll
    for (int r = 0; r < 4; r++)
#pragma unroll
        for (int c = 0; c < 8; c++) acc2[r][c] = 0ull;

    float4 a0r = avalid ? *reinterpret_cast<const float4*>(arow + aK)
                        : make_float4(0.f, 0.f, 0.f, 0.f);
    float4 b0r = *reinterpret_cast<const float4*>(Bm + (size_t)bK0 * CH + bN);
    float4 b1r = *reinterpret_cast<const float4*>(Bm + (size_t)bK1 * CH + bN);
    AsB[(aK+0)*132 + aRow] = a0r.x; AsB[(aK+1)*132 + aRow] = a0r.y;
    AsB[(aK+2)*132 + aRow] = a0r.z; AsB[(aK+3)*132 + aRow] = a0r.w;
    *reinterpret_cast<float4*>(&BsB[bK0*256 + bN]) = b0r;
    *reinterpret_cast<float4*>(&BsB[bK1*256 + bN]) = b1r;
    __syncthreads();

#pragma unroll 1
    for (int kb = 0; kb < 16; kb++) {
        const int cur = kb & 1;
        float* As = AsB + cur * (16 * 132);
        float* Bs = BsB + cur * (16 * 256);
        if (kb < 15) {
            int k0 = (kb + 1) * 16;
            a0r = avalid ? *reinterpret_cast<const float4*>(arow + k0 + aK)
                         : make_float4(0.f, 0.f, 0.f, 0.f);
            b0r = *reinterpret_cast<const float4*>(Bm + (size_t)(k0 + bK0) * CH + bN);
            b1r = *reinterpret_cast<const float4*>(Bm + (size_t)(k0 + bK1) * CH + bN);
        }
#pragma unroll
        for (int kk = 0; kk < 16; kk++) {
            ulonglong2 a01 = *reinterpret_cast<const ulonglong2*>(&As[kk*132 + tRow]);
            ulonglong2 a23 = *reinterpret_cast<const ulonglong2*>(&As[kk*132 + tRow + 4]);
            float4 b0 = *reinterpret_cast<const float4*>(&Bs[kk*256 + tCol]);
            float4 b1 = *reinterpret_cast<const float4*>(&Bs[kk*256 + tCol + 4]);
            unsigned long long av[4] = {a01.x, a01.y, a23.x, a23.y};
            float bf[8] = {b0.x, b0.y, b0.z, b0.w, b1.x, b1.y, b1.z, b1.w};
#pragma unroll
            for (int c = 0; c < 8; c++) {
                unsigned long long bc = bcast2(bf[c]);
#pragma unroll
                for (int r = 0; r < 4; r++)
                    acc2[r][c] = ffma2(av[r], bc, acc2[r][c]);
            }
        }
        if (kb < 15) {
            float* Asn = AsB + (cur ^ 1) * (16 * 132);
            float* Bsn = BsB + (cur ^ 1) * (16 * 256);
            Asn[(aK+0)*132 + aRow] = a0r.x; Asn[(aK+1)*132 + aRow] = a0r.y;
            Asn[(aK+2)*132 + aRow] = a0r.z; Asn[(aK+3)*132 + aRow] = a0r.w;
            *reinterpret_cast<float4*>(&Bsn[bK0*256 + bN]) = b0r;
            *reinterpret_cast<float4*>(&Bsn[bK1*256 + bN]) = b1r;
            __syncthreads();
        }
    }

    // ---- epilogue: bias + LayerNorm ----
    float4 bb0 = *reinterpret_cast<const float4*>(&bias[tCol]);
    float4 bb1 = *reinterpret_cast<const float4*>(&bias[tCol + 4]);
    float bcol[8] = {bb0.x, bb0.y, bb0.z, bb0.w, bb1.x, bb1.y, bb1.z, bb1.w};

    float mrow[4][2];
#pragma unroll
    for (int r2 = 0; r2 < 4; r2++)
#pragma unroll
        for (int half = 0; half < 2; half++) {
            float ps = 0.f;
#pragma unroll
            for (int c = 0; c < 8; c++) ps += pickhalf(acc2[r2][c], half) + bcol[c];
#pragma unroll
            for (int off = 4; off <= 16; off <<= 1)
                ps += __shfl_xor_sync(0xffffffffu, ps, off);
            if ((lane >> 2) == 0)
                red[wcg * 128 + tRow + 2 * r2 + half] = ps;
            mrow[r2][half] = 0.f;
        }
    __syncthreads();
#pragma unroll
    for (int r2 = 0; r2 < 4; r2++)
#pragma unroll
        for (int half = 0; half < 2; half++) {
            int lr = tRow + 2 * r2 + half;
            mrow[r2][half] = (red[lr] + red[128 + lr] + red[256 + lr] + red[384 + lr])
                             * (1.f / 256.f);
        }
    __syncthreads();
    float vrow[4][2];
#pragma unroll
    for (int r2 = 0; r2 < 4; r2++)
#pragma unroll
        for (int half = 0; half < 2; half++) {
            float m = mrow[r2][half];
            float ps = 0.f;
#pragma unroll
            for (int c = 0; c < 8; c++) {
                float d = pickhalf(acc2[r2][c], half) + bcol[c] - m;
                ps = fmaf(d, d, ps);
            }
#pragma unroll
            for (int off = 4; off <= 16; off <<= 1)
                ps += __shfl_xor_sync(0xffffffffu, ps, off);
            if ((lane >> 2) == 0)
                red[wcg * 128 + tRow + 2 * r2 + half] = ps;
            vrow[r2][half] = 0.f;
        }
    __syncthreads();
#pragma unroll
    for (int r2 = 0; r2 < 4; r2++)
#pragma unroll
        for (int half = 0; half < 2; half++) {
            int lr = tRow + 2 * r2 + half;
            vrow[r2][half] = (red[lr] + red[128 + lr] + red[256 + lr] + red[384 + lr])
                             * (1.f / 256.f);
        }

    float4 gg0 = *reinterpret_cast<const float4*>(&lng[tCol]);
    float4 gg1 = *reinterpret_cast<const float4*>(&lng[tCol + 4]);
    float4 ob0 = *reinterpret_cast<const float4*>(&lnb[tCol]);
    float4 ob1 = *reinterpret_cast<const float4*>(&lnb[tCol + 4]);
    float gcol[8] = {gg0.x, gg0.y, gg0.z, gg0.w, gg1.x, gg1.y, gg1.z, gg1.w};
    float ocol[8] = {ob0.x, ob0.y, ob0.z, ob0.w, ob1.x, ob1.y, ob1.z, ob1.w};

#pragma unroll
    for (int r2 = 0; r2 < 4; r2++)
#pragma unroll
        for (int half = 0; half < 2; half++) {
            int gr = rowBase + tRow + 2 * r2 + half;
            if (gr >= MROWS) continue;
            float m = mrow[r2][half];
            float inv = 1.f / sqrtf(vrow[r2][half] + 1e-5f);
            float o[8];
#pragma unroll
            for (int c = 0; c < 8; c++) {
                float x = pickhalf(acc2[r2][c], half) + bcol[c];
                o[c] = (x - m) * inv * gcol[c] + ocol[c];
            }
            float4 v0 = make_float4(o[0], o[1], o[2], o[3]);
            float4 v1 = make_float4(o[4], o[5], o[6], o[7]);
            *reinterpret_cast<float4*>(&Y[(size_t)gr * CH + tCol]) = v0;
            *reinterpret_cast<float4*>(&Y[(size_t)gr * CH + tCol + 4]) = v1;
        }
}

// ============ cls GEMM: logits = out_mem @ Wpad + b_cls, fused row-max =====
// 256 threads, tile 128x96, 8x6 microtile. B fill is a contiguous float4 copy.
__global__ void __launch_bounds__(256, 2)
cls_kernel(const float* __restrict__ A, const float* __restrict__ Wp,
           const float* __restrict__ bias, float* __restrict__ C,
           float* __restrict__ scores)
{
    __shared__ float As[2][16][132];
    __shared__ float Bs[2][16 * 96];

    const int tid = threadIdx.x;
    const int warp = tid >> 5, lane = tid & 31;
    const int rowBase = blockIdx.x * 128;

    const int tRow = (warp & 3) * 32 + (lane & 3) * 8;
    const int tCol = (warp >> 2) * 48 + (lane >> 2) * 6;

    const int aRow0 = tid >> 2, aK = (tid & 3) << 2, aRow1 = aRow0 + 64;

    unsigned long long acc2[4][6];
#pragma unroll
    for (int r = 0; r < 4; r++)
#pragma unroll
        for (int c = 0; c < 6; c++) acc2[r][c] = 0ull;

    auto loadArow = [&](int gr, int kOff) {
        if (gr < MROWS)
            return *reinterpret_cast<const float4*>(A + (size_t)gr * CH + kOff);
        return make_float4(0.f, 0.f, 0.f, 0.f);
    };
    // slab kb of Wp is contiguous: Wp[kb*16*96 .. +1536]
    auto fillB = [&](int kb, int buf) {
        const float4* src = reinterpret_cast<const float4*>(Wp + kb * 16 * NCP);
        float4* dst = reinterpret_cast<float4*>(&Bs[buf][0]);
#pragma unroll
        for (int i = tid; i < 384; i += 256) dst[i] = src[i];
    };

    float4 a0r = loadArow(rowBase + aRow0, aK);
    float4 a1r = loadArow(rowBase + aRow1, aK);
    As[0][aK+0][aRow0] = a0r.x; As[0][aK+1][aRow0] = a0r.y;
    As[0][aK+2][aRow0] = a0r.z; As[0][aK+3][aRow0] = a0r.w;
    As[0][aK+0][aRow1] = a1r.x; As[0][aK+1][aRow1] = a1r.y;
    As[0][aK+2][aRow1] = a1r.z; As[0][aK+3][aRow1] = a1r.w;
    fillB(0, 0);
    __syncthreads();

#pragma unroll 1
    for (int kb = 0; kb < 16; kb++) {
        const int cur = kb & 1;
        if (kb < 15) {
            a0r = loadArow(rowBase + aRow0, (kb + 1) * 16 + aK);
            a1r = loadArow(rowBase + aRow1, (kb + 1) * 16 + aK);
        }
#pragma unroll
        for (int kk = 0; kk < 16; kk++) {
            ulonglong2 a01 = *reinterpret_cast<const ulonglong2*>(&As[cur][kk][tRow]);
            ulonglong2 a23 = *reinterpret_cast<const ulonglong2*>(&As[cur][kk][tRow + 4]);
            const float* brow = &Bs[cur][kk * NCP + tCol];
            float2 b01 = *reinterpret_cast<const float2*>(brow);
            float2 b23 = *reinterpret_cast<const float2*>(brow + 2);
            float2 b45 = *reinterpret_cast<const float2*>(brow + 4);
            unsigned long long av[4] = {a01.x, a01.y, a23.x, a23.y};
            float bf[6] = {b01.x, b01.y, b23.x, b23.y, b45.x, b45.y};
#pragma unroll
            for (int c = 0; c < 6; c++) {
                unsigned long long bc = bcast2(bf[c]);
#pragma unroll
                for (int r = 0; r < 4; r++)
                    acc2[r][c] = ffma2(av[r], bc, acc2[r][c]);
            }
        }
        if (kb < 15) {
            const int nxt = 1 - cur;
            As[nxt][aK+0][aRow0] = a0r.x; As[nxt][aK+1][aRow0] = a0r.y;
            As[nxt][aK+2][aRow0] = a0r.z; As[nxt][aK+3][aRow0] = a0r.w;
            As[nxt][aK+0][aRow1] = a1r.x; As[nxt][aK+1][aRow1] = a1r.y;
            As[nxt][aK+2][aRow1] = a1r.z; As[nxt][aK+3][aRow1] = a1r.w;
            fillB(kb + 1, nxt);
            __syncthreads();
        }
    }

    // ---- epilogue: store logits (gc<91) + fused row-max ----
    float rmaxv[4][2];
#pragma unroll
    for (int r2 = 0; r2 < 4; r2++)
#pragma unroll
        for (int half = 0; half < 2; half++) {
            int gr = rowBase + tRow + 2 * r2 + half;
            float m = -INFINITY;
#pragma unroll
            for (int c = 0; c < 6; c++) {
                int gc = tCol + c;
                if (gc < NC) {
                    float v = pickhalf(acc2[r2][c], half) + bias[gc];
                    if (gr < MROWS) C[(size_t)gr * NC + gc] = v;
                    m = fmaxf(m, v);
                }
            }
            rmaxv[r2][half] = m;
        }
    __syncthreads();                      // all warps done reading As
    float* red = &As[0][0][0];            // reuse as [128][16]
    int slot = ((warp >> 2) << 3) | (lane >> 2);
#pragma unroll
    for (int r2 = 0; r2 < 4; r2++)
#pragma unroll
        for (int half = 0; half < 2; half++)
            red[(tRow + 2 * r2 + half) * 16 + slot] = rmaxv[r2][half];
    __syncthreads();
    if (tid < 128) {
        int gr = rowBase + tid;
        if (gr < MROWS) {
            float m = -INFINITY;
#pragma unroll
            for (int s = 0; s < 16; s++) m = fmaxf(m, red[tid * 16 + s]);
            scores[gr] = m;
        }
    }
}

// ============ top-k, two phase ==============================================
__global__ void topk1_kernel(const float* __restrict__ scores,
                             float* __restrict__ candV, int* __restrict__ candI)
{
    const int c = blockIdx.x, b = blockIdx.y;
    const int base = c * CHUNK;
    const int cnt = min(CHUNK, SEQ - base);
    __shared__ float vals[CHUNK];
    __shared__ float wv[8];
    __shared__ int   wi[8];
    const int tid = threadIdx.x, lane = tid & 31, warp = tid >> 5;

    for (int i = tid; i < cnt; i += 256) vals[i] = scores[(size_t)b * SEQ + base + i];
    __syncthreads();

    for (int it = 0; it < NTOP; it++) {
        float bv = -INFINITY; int bi = 0x7fffffff;
        for (int i = tid; i < cnt; i += 256) {
            float v = vals[i];
            if (v > bv || (v == bv && i < bi)) { bv = v; bi = i; }
        }
#pragma unroll
        for (int off = 16; off; off >>= 1) {
            float ov = __shfl_xor_sync(0xffffffffu, bv, off);
            int   oi = __shfl_xor_sync(0xffffffffu, bi, off);
            if (ov > bv || (ov == bv && oi < bi)) { bv = ov; bi = oi; }
        }
        if (lane == 0) { wv[warp] = bv; wi[warp] = bi; }
        __syncthreads();
        if (tid == 0) {
            float fv = wv[0]; int fi = wi[0];
#pragma unroll
            for (int w = 1; w < 8; w++)
                if (wv[w] > fv || (wv[w] == fv && wi[w] < fi)) { fv = wv[w]; fi = wi[w]; }
            int o = (b * CHUNKS + c) * NTOP + it;
            candV[o] = fv; candI[o] = base + fi;
            vals[fi] = -INFINITY;
        }
        __syncthreads();
    }
}

__global__ void topk2_kernel(const float* __restrict__ candV, const int* __restrict__ candI,
                             int* __restrict__ topIdx, float* __restrict__ topSc)
{
    const int b = blockIdx.x;
    const int NCAND = CHUNKS * NTOP;       // 320
    __shared__ float cv[NCAND];
    __shared__ int   ci[NCAND];
    __shared__ float wv[10];
    __shared__ int   wgi[10], wps[10];
    const int tid = threadIdx.x, lane = tid & 31, warp = tid >> 5;

    if (tid < NCAND) { cv[tid] = candV[b * NCAND + tid]; ci[tid] = candI[b * NCAND + tid]; }
    __syncthreads();

    for (int it = 0; it < NTOP; it++) {
        float v = (tid < NCAND) ? cv[tid] : -INFINITY;
        int gi = (tid < NCAND) ? ci[tid] : 0x7fffffff;
        int ps = tid;
#pragma unroll
        for (int off = 16; off; off >>= 1) {
            float ov = __shfl_xor_sync(0xffffffffu, v, off);
            int  ogi = __shfl_xor_sync(0xffffffffu, gi, off);
            int  ops = __shfl_xor_sync(0xffffffffu, ps, off);
            if (ov > v || (ov == v && ogi < gi)) { v = ov; gi = ogi; ps = ops; }
        }
        if (lane == 0) { wv[warp] = v; wgi[warp] = gi; wps[warp] = ps; }
        __syncthreads();
        if (tid == 0) {
            float fv = wv[0]; int fgi = wgi[0], fps = wps[0];
#pragma unroll
            for (int w = 1; w < 10; w++)
                if (wv[w] > fv || (wv[w] == fv && wgi[w] < fgi)) {
                    fv = wv[w]; fgi = wgi[w]; fps = wps[w];
                }
            topIdx[b * NTOP + it] = fgi;
            topSc[b * NTOP + it]  = fv;
            cv[fps] = -INFINITY;
        }
        __syncthreads();
    }
}

// ---------------- tiny MLP on top-k rows only --------------------------------
__global__ void tinymlp_kernel(const float* __restrict__ outmem,
                               const unsigned char* __restrict__ mask,
                               const float* __restrict__ W1, const float* __restrict__ b1,
                               const float* __restrict__ W2, const float* __restrict__ b2,
                               const float* __restrict__ W3, const float* __restrict__ b3,
                               const int* __restrict__ topIdx,
                               float* __restrict__ coordsTop)
{
    __shared__ float s0[256], s1[256];
    const int blk = blockIdx.x;               // 0..159
    const int b = blk / NTOP;
    const int s = topIdx[blk];                // within-batch index
    const size_t row = (size_t)b * SEQ + s;
    const int tid = threadIdx.x;

    s0[tid] = outmem[row * CH + tid];
    __syncthreads();

    float acc = 0.f;
#pragma unroll 8
    for (int kk = 0; kk < CH; kk++) acc = fmaf(s0[kk], W1[kk * CH + tid], acc);
    s1[tid] = fmaxf(acc + b1[tid], 0.f);
    __syncthreads();

    acc = 0.f;
#pragma unroll 8
    for (int kk = 0; kk < CH; kk++) acc = fmaf(s1[kk], W2[kk * CH + tid], acc);
    float h2 = fmaxf(acc + b2[tid], 0.f);
    __syncthreads();
    s0[tid] = h2;
    __syncthreads();

    const int warp = tid >> 5, lane = tid & 31;
    if (warp < 4) {
        float a = 0.f;
        for (int kk = lane; kk < CH; kk += 32)
            a = fmaf(s0[kk], W3[kk * 4 + warp], a);
#pragma unroll
        for (int off = 16; off; off >>= 1) a += __shfl_xor_sync(0xffffffffu, a, off);
        if (lane == 0) {
            int Hh, Ww, t;
            if (s < 15000)      { Hh = 100; Ww = 150; t = s; }
            else if (s < 18750) { Hh = 50;  Ww = 75;  t = s - 15000; }
            else if (s < 19700) { Hh = 25;  Ww = 38;  t = s - 18750; }
            else                { Hh = 13;  Ww = 19;  t = s - 19700; }
            int lvl = (s < 15000) ? 0 : (s < 18750) ? 1 : (s < 19700) ? 2 : 3;
            int y = t / Ww, x = t % Ww;
            float cx = ((float)x + 0.5f) / (float)Ww;
            float cy = ((float)y + 0.5f) / (float)Hh;
            float wh = 0.05f * (float)(1 << lvl);
            bool valid = (cx > 0.01f) && (cx < 0.99f) &&
                         (cy > 0.01f) && (cy < 0.99f);
            bool inv = (mask[row] != 0) || !valid;
            float pv;
            if (inv) pv = INFINITY;
            else {
                float comp = (warp == 0) ? cx : (warp == 1) ? cy : wh;
                pv = logf(comp / (1.f - comp));
            }
            coordsTop[blk * 4 + warp] = a + b3[warp] + pv;
        }
    }
}

// ---------------- final: gather + sigmoid + boxes + NMS ----------------------
__global__ void final_kernel(const float* __restrict__ logits,
                             const float* __restrict__ coordsTop,
                             const int* __restrict__ topIdx, const float* __restrict__ topSc,
                             const float* __restrict__ WH, float* __restrict__ out)
{
    int b = blockIdx.x, tid = threadIdx.x;
    __shared__ int   idxs[NTOP];
    __shared__ float refp[NTOP][4];
    __shared__ float boxes[NTOP][4];
    if (tid < NTOP) idxs[tid] = topIdx[b * NTOP + tid];
    __syncthreads();

    for (int o = tid; o < NTOP * NC; o += blockDim.x) {
        int k = o / NC, c = o % NC;
        size_t row = (size_t)b * SEQ + idxs[k];
        out[OFF_OUT + b * (NTOP * (NC + 4)) + k * (NC + 4) + c] = logits[row * NC + c];
    }
    if (tid < NTOP * 4) {
        int k = tid >> 2, c = tid & 3;
        float v = coordsTop[(b * NTOP + k) * 4 + c];
        out[OFF_OUT + b * (NTOP * (NC + 4)) + k * (NC + 4) + NC + c] = v;
        float r = 1.f / (1.f + expf(-v));
        out[OFF_REF + b * (NTOP * 4) + k * 4 + c] = r;
        refp[k][c] = r;
    }
    if (tid < NTOP) out[OFF_SC + b * NTOP + tid] = topSc[b * NTOP + tid];
    __syncthreads();
    if (tid < NTOP) {
        float cx = refp[tid][0], cy = refp[tid][1], w = refp[tid][2], h = refp[tid][3];
        boxes[tid][0] = truncf((cx - 0.5f * w) * WH[b * 4 + 0]);
        boxes[tid][1] = truncf((cy - 0.5f * h) * WH[b * 4 + 1]);
        boxes[tid][2] = truncf((cx + 0.5f * w) * WH[b * 4 + 2]);
        boxes[tid][3] = truncf((cy + 0.5f * h) * WH[b * 4 + 3]);
    }
    __syncthreads();
    if (tid == 0) {
        bool supp[NTOP];
        float area[NTOP];
        for (int k = 0; k < NTOP; k++) {
            supp[k] = false;
            area[k] = (boxes[k][2] - boxes[k][0]) * (boxes[k][3] - boxes[k][1]);
        }
        for (int i = 0; i < NTOP; i++) {
            if (supp[i]) continue;
            for (int j = i + 1; j < NTOP; j++) {
                float xx1 = fmaxf(boxes[i][0], boxes[j][0]);
                float yy1 = fmaxf(boxes[i][1], boxes[j][1]);
                float xx2 = fminf(boxes[i][2], boxes[j][2]);
                float yy2 = fminf(boxes[i][3], boxes[j][3]);
                float inter = fmaxf(xx2 - xx1, 0.f) * fmaxf(yy2 - yy1, 0.f);
                float iou = inter / (area[i] + area[j] - inter);
                if (iou > 0.5f) supp[j] = true;
            }
        }
        for (int k = 0; k < NTOP; k++)
            out[OFF_KEEP + b * NTOP + k] = supp[k] ? 0.f : 1.f;
    }
}

// ---------------- launch -----------------------------------------------------
extern "C" void kernel_launch(void* const* d_in, const int* in_sizes, int n_in,
                              void* d_out, int out_size)
{
    const float* memory        = (const float*)d_in[0];
    const unsigned char* mask  = (const unsigned char*)d_in[1];
    const float* WH            = (const float*)d_in[2];
    const float* W_enc         = (const float*)d_in[3];
    const float* b_enc         = (const float*)d_in[4];
    const float* ln_g          = (const float*)d_in[5];
    const float* ln_b          = (const float*)d_in[6];
    const float* W_cls         = (const float*)d_in[7];
    const float* b_cls         = (const float*)d_in[8];
    const float* W1            = (const float*)d_in[9];
    const float* b1            = (const float*)d_in[10];
    const float* W2            = (const float*)d_in[11];
    const float* b2            = (const float*)d_in[12];
    const float* W3            = (const float*)d_in[13];
    const float* b3            = (const float*)d_in[14];
    float* out = (float*)d_out;

    float *p_outmem, *p_logits, *p_scores, *p_topsc, *p_ctop, *p_candV, *p_wpad;
    int *p_topidx, *p_candI;
    cudaGetSymbolAddress((void**)&p_outmem,  g_outmem);
    cudaGetSymbolAddress((void**)&p_logits,  g_logits);
    cudaGetSymbolAddress((void**)&p_scores,  g_scores);
    cudaGetSymbolAddress((void**)&p_topidx,  g_topidx);
    cudaGetSymbolAddress((void**)&p_topsc,   g_topsc);
    cudaGetSymbolAddress((void**)&p_ctop,    g_ctop);
    cudaGetSymbolAddress((void**)&p_candV,   g_candV);
    cudaGetSymbolAddress((void**)&p_candI,   g_candI);
    cudaGetSymbolAddress((void**)&p_wpad,    g_wpad);

    cudaFuncSetAttribute(gemm_ln_kernel,
                         cudaFuncAttributeMaxDynamicSharedMemorySize, GL_SMEM_BYTES);

    const int gRows = (MROWS + 127) / 128;   // 1247
    // pad W_cls -> [256][96]
    wpad_kernel<<<(CH * NCP + 255) / 256, 256>>>(W_cls, p_wpad);
    // out_mem = LN(mem_masked @ W_enc + b_enc)
    gemm_ln_kernel<<<gRows, 512, GL_SMEM_BYTES>>>(memory, mask, W_enc, b_enc,
                                                  ln_g, ln_b, p_outmem);
    // logits = out_mem @ Wpad + b_cls, fused row-max -> scores
    cls_kernel<<<gRows, 256>>>(p_outmem, p_wpad, b_cls, p_logits, p_scores);
    // top-20 per batch (two-phase)
    topk1_kernel<<<dim3(CHUNKS, BSZ), 256>>>(p_scores, p_candV, p_candI);
    topk2_kernel<<<BSZ, 320>>>(p_candV, p_candI, p_topidx, p_topsc);
    // MLP + coords only on the 160 selected rows
    tinymlp_kernel<<<BSZ * NTOP, 256>>>(p_outmem, mask, W1, b1, W2, b2, W3, b3,
                                        p_topidx, p_ctop);
    // gather + sigmoid + NMS + writes
    final_kernel<<<BSZ, 128>>>(p_logits, p_ctop, p_topidx, p_topsc, WH, out);

    (void)in_sizes; (void)n_in; (void)out_size;
}

// round 15
// speedup vs baseline: 3.5793x; 1.0059x over previous
#include <cuda_runtime.h>
#include <math.h>
#include <stdint.h>
#include <string.h>

#define BSZ   8
#define SEQ   19947
#define MROWS 159576          // BSZ*SEQ
#define CH    256
#define NC    91
#define NCP   96              // padded cls width
#define NTOP  20
#define CHUNKS 16
#define CHUNK  1247           // ceil(SEQ/16); last chunk = 1242

// output layout (float32, concatenated flattened tuple)
#define OFF_OUT  0            // (8,20,95)
#define OFF_REF  15200        // (8,20,4)
#define OFF_KEEP 15840        // (8,20)
#define OFF_SC   16000        // (8,20)

// ---------------- scratch (device globals: allocation-free) ----------------
__device__ float g_outmem[MROWS * CH];
__device__ float g_scores[MROWS];
__device__ int   g_topidx[BSZ * NTOP];
__device__ float g_topsc[BSZ * NTOP];
__device__ float g_ctop[BSZ * NTOP * 4];
__device__ float g_toplog[BSZ * NTOP * NC];
__device__ float g_candV[BSZ * CHUNKS * NTOP];
__device__ int   g_candI[BSZ * CHUNKS * NTOP];
__device__ float g_wpad[CH * NCP];        // W_cls padded to [256][96]

// ---------------- packed f32x2 helpers (Blackwell FFMA2) -------------------
__device__ __forceinline__ unsigned long long ffma2(unsigned long long a,
                                                    unsigned long long b,
                                                    unsigned long long c)
{
    unsigned long long d;
    asm("fma.rn.f32x2 %0, %1, %2, %3;" : "=l"(d) : "l"(a), "l"(b), "l"(c));
    return d;
}
__device__ __forceinline__ unsigned long long bcast2(float x)
{
    unsigned long long d;
    unsigned int xi = __float_as_uint(x);
    asm("mov.b64 %0, {%1, %1};" : "=l"(d) : "r"(xi));
    return d;
}
__device__ __forceinline__ float pickhalf(unsigned long long v, int half)
{
    float2 p;
    memcpy(&p, &v, 8);
    return half ? p.y : p.x;
}

// row validity by geometry + mask (reference _gen_proposals semantics)
__device__ __forceinline__ bool row_valid_geom(int s)
{
    int Hh, Ww, t;
    if (s < 15000)      { Hh = 100; Ww = 150; t = s; }
    else if (s < 18750) { Hh = 50;  Ww = 75;  t = s - 15000; }
    else if (s < 19700) { Hh = 25;  Ww = 38;  t = s - 18750; }
    else                { Hh = 13;  Ww = 19;  t = s - 19700; }
    int y = t / Ww, x = t % Ww;
    float cx = ((float)x + 0.5f) / (float)Ww;
    float cy = ((float)y + 0.5f) / (float)Hh;
    return (cx > 0.01f) && (cx < 0.99f) && (cy > 0.01f) && (cy < 0.99f);
}

// ---------------- pad W_cls [256][91] -> [256][96] ---------------------------
__global__ void wpad_kernel(const float* __restrict__ Wc, float* __restrict__ Wp)
{
    int idx = blockIdx.x * 256 + threadIdx.x;
    if (idx >= CH * NCP) return;
    int k = idx / NCP, n = idx % NCP;
    Wp[idx] = (n < NC) ? Wc[k * NC + n] : 0.f;
}

// ============ FUSED: GEMM1 + bias + LayerNorm + cls rowmax ===================
// Phase A: out_mem tile = LN(mem_masked @ W_enc + b_enc)  (write Y + smem LP)
// Phase B: scores[rows] = rowmax(LP @ Wpad + b_cls)       (A never re-read)
//
// smem floats:
//   [0 .. 4224)        phase-A As double buffer       | phase-B Ws double buf (3200)
//   [4224 .. 12416)    phase-A Bs double buffer       | phase-B redB (2048)
//   [12416 .. 12928)   phase-A red
//   [12928 .. 47744)   LP: [k=256][136] row-pair packed, XOR-swizzled
#define GL_AS 0
#define GL_BS 4224
#define GL_RED 12416
#define LP_OFF 12928
#define GL_SMEM_FLOATS (12928 + 256 * 136)
#define GL_SMEM_BYTES (GL_SMEM_FLOATS * 4)

__global__ void __launch_bounds__(512, 1)
gemm_fused_kernel(const float* __restrict__ A, const unsigned char* __restrict__ mask,
                  const float* __restrict__ Bm, const float* __restrict__ bias,
                  const float* __restrict__ lng, const float* __restrict__ lnb,
                  const float* __restrict__ Wp, const float* __restrict__ bcls,
                  float* __restrict__ Y, float* __restrict__ scores)
{
    extern __shared__ float smf[];
    float* AsB = smf + GL_AS;     // [buf][16][132]
    float* BsB = smf + GL_BS;     // [buf][16][256]
    float* red = smf + GL_RED;    // [4][128]

    const int tid = threadIdx.x;
    const int warp = tid >> 5, lane = tid & 31;
    const int rowBase = blockIdx.x * 128;

    const int tRow = (warp & 3) * 32 + (lane & 3) * 8;
    const int tCol = (warp >> 2) * 64 + (lane >> 2) * 8;
    const int wcg  = warp >> 2;
    const int qA   = (warp & 3) * 4 + (lane & 3);   // pair-block id for LP writes

    const int aRow = tid >> 2, aK = (tid & 3) << 2;
    const int agr = rowBase + aRow;
    bool avalid = false;
    if (agr < MROWS) {
        int s = agr % SEQ;
        avalid = (mask[agr] == 0) && row_valid_geom(s);
    }
    const float* arow = A + (size_t)agr * CH;
    const int bK0 = tid >> 6, bN = (tid & 63) << 2, bK1 = bK0 + 8;

    unsigned long long acc2[4][8];
#pragma unroll
    for (int r = 0; r < 4; r++)
#pragma unroll
        for (int c = 0; c < 8; c++) acc2[r][c] = 0ull;

    float4 a0r = avalid ? *reinterpret_cast<const float4*>(arow + aK)
                        : make_float4(0.f, 0.f, 0.f, 0.f);
    float4 b0r = *reinterpret_cast<const float4*>(Bm + (size_t)bK0 * CH + bN);
    float4 b1r = *reinterpret_cast<const float4*>(Bm + (size_t)bK1 * CH + bN);
    AsB[(aK+0)*132 + aRow] = a0r.x; AsB[(aK+1)*132 + aRow] = a0r.y;
    AsB[(aK+2)*132 + aRow] = a0r.z; AsB[(aK+3)*132 + aRow] = a0r.w;
    *reinterpret_cast<float4*>(&BsB[bK0*256 + bN]) = b0r;
    *reinterpret_cast<float4*>(&BsB[bK1*256 + bN]) = b1r;
    __syncthreads();

#pragma unroll 1
    for (int kb = 0; kb < 16; kb++) {
        const int cur = kb & 1;
        float* As = AsB + cur * (16 * 132);
        float* Bs = BsB + cur * (16 * 256);
        if (kb < 15) {
            int k0 = (kb + 1) * 16;
            a0r = avalid ? *reinterpret_cast<const float4*>(arow + k0 + aK)
                         : make_float4(0.f, 0.f, 0.f, 0.f);
            b0r = *reinterpret_cast<const float4*>(Bm + (size_t)(k0 + bK0) * CH + bN);
            b1r = *reinterpret_cast<const float4*>(Bm + (size_t)(k0 + bK1) * CH + bN);
        }
#pragma unroll
        for (int kk = 0; kk < 16; kk++) {
            ulonglong2 a01 = *reinterpret_cast<const ulonglong2*>(&As[kk*132 + tRow]);
            ulonglong2 a23 = *reinterpret_cast<const ulonglong2*>(&As[kk*132 + tRow + 4]);
            float4 b0 = *reinterpret_cast<const float4*>(&Bs[kk*256 + tCol]);
            float4 b1 = *reinterpret_cast<const float4*>(&Bs[kk*256 + tCol + 4]);
            unsigned long long av[4] = {a01.x, a01.y, a23.x, a23.y};
            float bf[8] = {b0.x, b0.y, b0.z, b0.w, b1.x, b1.y, b1.z, b1.w};
#pragma unroll
            for (int c = 0; c < 8; c++) {
                unsigned long long bc = bcast2(bf[c]);
#pragma unroll
                for (int r = 0; r < 4; r++)
                    acc2[r][c] = ffma2(av[r], bc, acc2[r][c]);
            }
        }
        if (kb < 15) {
            float* Asn = AsB + (cur ^ 1) * (16 * 132);
            float* Bsn = BsB + (cur ^ 1) * (16 * 256);
            Asn[(aK+0)*132 + aRow] = a0r.x; Asn[(aK+1)*132 + aRow] = a0r.y;
            Asn[(aK+2)*132 + aRow] = a0r.z; Asn[(aK+3)*132 + aRow] = a0r.w;
            *reinterpret_cast<float4*>(&Bsn[bK0*256 + bN]) = b0r;
            *reinterpret_cast<float4*>(&Bsn[bK1*256 + bN]) = b1r;
            __syncthreads();
        }
    }

    // ---- phase A epilogue: bias + LayerNorm ----
    float4 bb0 = *reinterpret_cast<const float4*>(&bias[tCol]);
    float4 bb1 = *reinterpret_cast<const float4*>(&bias[tCol + 4]);
    float bcol[8] = {bb0.x, bb0.y, bb0.z, bb0.w, bb1.x, bb1.y, bb1.z, bb1.w};

    float mrow[4][2];
#pragma unroll
    for (int r2 = 0; r2 < 4; r2++)
#pragma unroll
        for (int half = 0; half < 2; half++) {
            float ps = 0.f;
#pragma unroll
            for (int c = 0; c < 8; c++) ps += pickhalf(acc2[r2][c], half) + bcol[c];
#pragma unroll
            for (int off = 4; off <= 16; off <<= 1)
                ps += __shfl_xor_sync(0xffffffffu, ps, off);
            if ((lane >> 2) == 0)
                red[wcg * 128 + tRow + 2 * r2 + half] = ps;
            mrow[r2][half] = 0.f;
        }
    __syncthreads();
#pragma unroll
    for (int r2 = 0; r2 < 4; r2++)
#pragma unroll
        for (int half = 0; half < 2; half++) {
            int lr = tRow + 2 * r2 + half;
            mrow[r2][half] = (red[lr] + red[128 + lr] + red[256 + lr] + red[384 + lr])
                             * (1.f / 256.f);
        }
    __syncthreads();
    float vrow[4][2];
#pragma unroll
    for (int r2 = 0; r2 < 4; r2++)
#pragma unroll
        for (int half = 0; half < 2; half++) {
            float m = mrow[r2][half];
            float ps = 0.f;
#pragma unroll
            for (int c = 0; c < 8; c++) {
                float d = pickhalf(acc2[r2][c], half) + bcol[c] - m;
                ps = fmaf(d, d, ps);
            }
#pragma unroll
            for (int off = 4; off <= 16; off <<= 1)
                ps += __shfl_xor_sync(0xffffffffu, ps, off);
            if ((lane >> 2) == 0)
                red[wcg * 128 + tRow + 2 * r2 + half] = ps;
            vrow[r2][half] = 0.f;
        }
    __syncthreads();
#pragma unroll
    for (int r2 = 0; r2 < 4; r2++)
#pragma unroll
        for (int half = 0; half < 2; half++) {
            int lr = tRow + 2 * r2 + half;
            vrow[r2][half] = (red[lr] + red[128 + lr] + red[256 + lr] + red[384 + lr])
                             * (1.f / 256.f);
        }

    float4 gg0 = *reinterpret_cast<const float4*>(&lng[tCol]);
    float4 gg1 = *reinterpret_cast<const float4*>(&lng[tCol + 4]);
    float4 ob0 = *reinterpret_cast<const float4*>(&lnb[tCol]);
    float4 ob1 = *reinterpret_cast<const float4*>(&lnb[tCol + 4]);
    float gcol[8] = {gg0.x, gg0.y, gg0.z, gg0.w, gg1.x, gg1.y, gg1.z, gg1.w};
    float ocol[8] = {ob0.x, ob0.y, ob0.z, ob0.w, ob1.x, ob1.y, ob1.z, ob1.w};

#pragma unroll
    for (int r2 = 0; r2 < 4; r2++) {
        float o2[2][8];
#pragma unroll
        for (int half = 0; half < 2; half++) {
            float m = mrow[r2][half];
            float inv = 1.f / sqrtf(vrow[r2][half] + 1e-5f);
#pragma unroll
            for (int c = 0; c < 8; c++) {
                float x = pickhalf(acc2[r2][c], half) + bcol[c];
                o2[half][c] = (x - m) * inv * gcol[c] + ocol[c];
            }
        }
        // global Y
#pragma unroll
        for (int half = 0; half < 2; half++) {
            int gr = rowBase + tRow + 2 * r2 + half;
            if (gr < MROWS) {
                float4 v0 = make_float4(o2[half][0], o2[half][1], o2[half][2], o2[half][3]);
                float4 v1 = make_float4(o2[half][4], o2[half][5], o2[half][6], o2[half][7]);
                *reinterpret_cast<float4*>(&Y[(size_t)gr * CH + tCol]) = v0;
                *reinterpret_cast<float4*>(&Y[(size_t)gr * CH + tCol + 4]) = v1;
            }
        }
        // LP smem: pair (row 2p, 2p+1) at block q=qA, slot j=r2, XOR-swizzled by k>>3
#pragma unroll
        for (int c = 0; c < 8; c++) {
            int k = tCol + c;
            int pp = ((qA ^ ((k >> 3) & 15)) << 2) | r2;
            *reinterpret_cast<float2*>(smf + LP_OFF + k * 136 + 2 * pp) =
                make_float2(o2[0][c], o2[1][c]);
        }
    }

    // ================= phase B: scores = rowmax(LP @ Wpad + bcls) ============
    __syncthreads();   // LP complete; phase-A As/Bs dead
    float* Ws  = smf;            // [buf][16][100] = 2*1600 floats
    float* redB = smf + GL_BS;   // [128][16]

    const int rowsB = (warp & 7) * 16 + (lane & 3) * 4;     // 4 rows per thread
    const int qB    = (warp & 7) * 2 + ((lane & 3) >> 1);
    const int jbase = ((lane & 3) & 1) * 2;
    const int tColB = (warp >> 3) * 48 + (lane >> 2) * 6;

    unsigned long long accB[2][6];
#pragma unroll
    for (int r = 0; r < 2; r++)
#pragma unroll
        for (int c = 0; c < 6; c++) accB[r][c] = 0ull;

    // fill slab 0
    for (int i = tid; i < 16 * NCP; i += 512)
        Ws[(i / NCP) * 100 + (i % NCP)] = Wp[i];
    __syncthreads();

#pragma unroll 1
    for (int sb = 0; sb < 16; sb++) {
        const int cur = sb & 1;
        float wr0 = 0.f, wr1 = 0.f, wr2 = 0.f;
        if (sb < 15) {
            const float* src = Wp + (sb + 1) * (16 * NCP);
            wr0 = src[tid]; wr1 = src[tid + 512]; wr2 = src[tid + 1024];
        }
        const float* Wc = Ws + cur * 1600;
#pragma unroll
        for (int kk = 0; kk < 16; kk++) {
            int k = sb * 16 + kk;
            int qx = qB ^ ((k >> 3) & 15);
            ulonglong2 av2 = *reinterpret_cast<const ulonglong2*>(
                smf + LP_OFF + k * 136 + 2 * ((qx << 2) + jbase));
            const float* brow = Wc + kk * 100 + tColB;
            float2 b01 = *reinterpret_cast<const float2*>(brow);
            float2 b23 = *reinterpret_cast<const float2*>(brow + 2);
            float2 b45 = *reinterpret_cast<const float2*>(brow + 4);
            unsigned long long av[2] = {av2.x, av2.y};
            float bf[6] = {b01.x, b01.y, b23.x, b23.y, b45.x, b45.y};
#pragma unroll
            for (int c = 0; c < 6; c++) {
                unsigned long long bc = bcast2(bf[c]);
                accB[0][c] = ffma2(av[0], bc, accB[0][c]);
                accB[1][c] = ffma2(av[1], bc, accB[1][c]);
            }
        }
        if (sb < 15) {
            float* Wn = Ws + (cur ^ 1) * 1600;
            Wn[(tid / NCP) * 100 + (tid % NCP)] = wr0;
            Wn[((tid + 512) / NCP) * 100 + ((tid + 512) % NCP)] = wr1;
            Wn[((tid + 1024) / NCP) * 100 + ((tid + 1024) % NCP)] = wr2;
        }
        __syncthreads();
    }

    // rowmax over this thread's 4 rows x 6 cols (+bias, guarded to gc<91)
    float mB[4] = {-INFINITY, -INFINITY, -INFINITY, -INFINITY};
#pragma unroll
    for (int r2 = 0; r2 < 2; r2++)
#pragma unroll
        for (int half = 0; half < 2; half++) {
            int r = 2 * r2 + half;
#pragma unroll
            for (int c = 0; c < 6; c++) {
                int gc = tColB + c;
                if (gc < NC)
                    mB[r] = fmaxf(mB[r], pickhalf(accB[r2][c], half) + bcls[gc]);
            }
        }
    const int slot = ((warp >> 3) << 3) | (lane >> 2);
#pragma unroll
    for (int r = 0; r < 4; r++)
        redB[(rowsB + r) * 16 + slot] = mB[r];
    __syncthreads();
    if (tid < 128) {
        int gr = rowBase + tid;
        if (gr < MROWS) {
            float m = -INFINITY;
#pragma unroll
            for (int s = 0; s < 16; s++) m = fmaxf(m, redB[tid * 16 + s]);
            scores[gr] = m;
        }
    }
}

// ============ top-k, two phase ==============================================
__global__ void topk1_kernel(const float* __restrict__ scores,
                             float* __restrict__ candV, int* __restrict__ candI)
{
    const int c = blockIdx.x, b = blockIdx.y;
    const int base = c * CHUNK;
    const int cnt = min(CHUNK, SEQ - base);
    __shared__ float vals[CHUNK];
    __shared__ float wv[8];
    __shared__ int   wi[8];
    const int tid = threadIdx.x, lane = tid & 31, warp = tid >> 5;

    for (int i = tid; i < cnt; i += 256) vals[i] = scores[(size_t)b * SEQ + base + i];
    __syncthreads();

    for (int it = 0; it < NTOP; it++) {
        float bv = -INFINITY; int bi = 0x7fffffff;
        for (int i = tid; i < cnt; i += 256) {
            float v = vals[i];
            if (v > bv || (v == bv && i < bi)) { bv = v; bi = i; }
        }
#pragma unroll
        for (int off = 16; off; off >>= 1) {
            float ov = __shfl_xor_sync(0xffffffffu, bv, off);
            int   oi = __shfl_xor_sync(0xffffffffu, bi, off);
            if (ov > bv || (ov == bv && oi < bi)) { bv = ov; bi = oi; }
        }
        if (lane == 0) { wv[warp] = bv; wi[warp] = bi; }
        __syncthreads();
        if (tid == 0) {
            float fv = wv[0]; int fi = wi[0];
#pragma unroll
            for (int w = 1; w < 8; w++)
                if (wv[w] > fv || (wv[w] == fv && wi[w] < fi)) { fv = wv[w]; fi = wi[w]; }
            int o = (b * CHUNKS + c) * NTOP + it;
            candV[o] = fv; candI[o] = base + fi;
            vals[fi] = -INFINITY;
        }
        __syncthreads();
    }
}

__global__ void topk2_kernel(const float* __restrict__ candV, const int* __restrict__ candI,
                             int* __restrict__ topIdx, float* __restrict__ topSc)
{
    const int b = blockIdx.x;
    const int NCAND = CHUNKS * NTOP;       // 320
    __shared__ float cv[NCAND];
    __shared__ int   ci[NCAND];
    __shared__ float wv[10];
    __shared__ int   wgi[10], wps[10];
    const int tid = threadIdx.x, lane = tid & 31, warp = tid >> 5;

    if (tid < NCAND) { cv[tid] = candV[b * NCAND + tid]; ci[tid] = candI[b * NCAND + tid]; }
    __syncthreads();

    for (int it = 0; it < NTOP; it++) {
        float v = (tid < NCAND) ? cv[tid] : -INFINITY;
        int gi = (tid < NCAND) ? ci[tid] : 0x7fffffff;
        int ps = tid;
#pragma unroll
        for (int off = 16; off; off >>= 1) {
            float ov = __shfl_xor_sync(0xffffffffu, v, off);
            int  ogi = __shfl_xor_sync(0xffffffffu, gi, off);
            int  ops = __shfl_xor_sync(0xffffffffu, ps, off);
            if (ov > v || (ov == v && ogi < gi)) { v = ov; gi = ogi; ps = ops; }
        }
        if (lane == 0) { wv[warp] = v; wgi[warp] = gi; wps[warp] = ps; }
        __syncthreads();
        if (tid == 0) {
            float fv = wv[0]; int fgi = wgi[0], fps = wps[0];
#pragma unroll
            for (int w = 1; w < 10; w++)
                if (wv[w] > fv || (wv[w] == fv && wgi[w] < fgi)) {
                    fv = wv[w]; fgi = wgi[w]; fps = wps[w];
                }
            topIdx[b * NTOP + it] = fgi;
            topSc[b * NTOP + it]  = fv;
            cv[fps] = -INFINITY;
        }
        __syncthreads();
    }
}

// ---------------- tiny MLP + logits on top-k rows only -----------------------
__global__ void tinymlp_kernel(const float* __restrict__ outmem,
                               const unsigned char* __restrict__ mask,
                               const float* __restrict__ W1, const float* __restrict__ b1,
                               const float* __restrict__ W2, const float* __restrict__ b2,
                               const float* __restrict__ W3, const float* __restrict__ b3,
                               const float* __restrict__ Wc, const float* __restrict__ bcls,
                               const int* __restrict__ topIdx,
                               float* __restrict__ coordsTop,
                               float* __restrict__ topLog)
{
    __shared__ float s0[256], s1[256];
    const int blk = blockIdx.x;               // 0..159
    const int b = blk / NTOP;
    const int s = topIdx[blk];                // within-batch index
    const size_t row = (size_t)b * SEQ + s;
    const int tid = threadIdx.x;

    s0[tid] = outmem[row * CH + tid];
    __syncthreads();

    // logits for this row (threads 0..90): coalesced W_cls reads
    if (tid < NC) {
        float acc = bcls[tid];
#pragma unroll 8
        for (int kk = 0; kk < CH; kk++) acc = fmaf(s0[kk], Wc[kk * NC + tid], acc);
        topLog[blk * NC + tid] = acc;
    }

    float acc = 0.f;
#pragma unroll 8
    for (int kk = 0; kk < CH; kk++) acc = fmaf(s0[kk], W1[kk * CH + tid], acc);
    s1[tid] = fmaxf(acc + b1[tid], 0.f);
    __syncthreads();

    acc = 0.f;
#pragma unroll 8
    for (int kk = 0; kk < CH; kk++) acc = fmaf(s1[kk], W2[kk * CH + tid], acc);
    float h2 = fmaxf(acc + b2[tid], 0.f);
    __syncthreads();
    s0[tid] = h2;
    __syncthreads();

    const int warp = tid >> 5, lane = tid & 31;
    if (warp < 4) {
        float a = 0.f;
        for (int kk = lane; kk < CH; kk += 32)
            a = fmaf(s0[kk], W3[kk * 4 + warp], a);
#pragma unroll
        for (int off = 16; off; off >>= 1) a += __shfl_xor_sync(0xffffffffu, a, off);
        if (lane == 0) {
            int Hh, Ww, t;
            if (s < 15000)      { Hh = 100; Ww = 150; t = s; }
            else if (s < 18750) { Hh = 50;  Ww = 75;  t = s - 15000; }
            else if (s < 19700) { Hh = 25;  Ww = 38;  t = s - 18750; }
            else                { Hh = 13;  Ww = 19;  t = s - 19700; }
            int lvl = (s < 15000) ? 0 : (s < 18750) ? 1 : (s < 19700) ? 2 : 3;
            int y = t / Ww, x = t % Ww;
            float cx = ((float)x + 0.5f) / (float)Ww;
            float cy = ((float)y + 0.5f) / (float)Hh;
            float wh = 0.05f * (float)(1 << lvl);
            bool valid = (cx > 0.01f) && (cx < 0.99f) &&
                         (cy > 0.01f) && (cy < 0.99f);
            bool inv = (mask[row] != 0) || !valid;
            float pv;
            if (inv) pv = INFINITY;
            else {
                float comp = (warp == 0) ? cx : (warp == 1) ? cy : wh;
                pv = logf(comp / (1.f - comp));
            }
            coordsTop[blk * 4 + warp] = a + b3[warp] + pv;
        }
    }
}

// ---------------- final: gather + sigmoid + boxes + NMS ----------------------
__global__ void final_kernel(const float* __restrict__ topLog,
                             const float* __restrict__ coordsTop,
                             const int* __restrict__ topIdx, const float* __restrict__ topSc,
                             const float* __restrict__ WH, float* __restrict__ out)
{
    int b = blockIdx.x, tid = threadIdx.x;
    __shared__ float refp[NTOP][4];
    __shared__ float boxes[NTOP][4];

    for (int o = tid; o < NTOP * NC; o += blockDim.x) {
        int k = o / NC, c = o % NC;
        out[OFF_OUT + b * (NTOP * (NC + 4)) + k * (NC + 4) + c] =
            topLog[(b * NTOP + k) * NC + c];
    }
    if (tid < NTOP * 4) {
        int k = tid >> 2, c = tid & 3;
        float v = coordsTop[(b * NTOP + k) * 4 + c];
        out[OFF_OUT + b * (NTOP * (NC + 4)) + k * (NC + 4) + NC + c] = v;
        float r = 1.f / (1.f + expf(-v));
        out[OFF_REF + b * (NTOP * 4) + k * 4 + c] = r;
        refp[k][c] = r;
    }
    if (tid < NTOP) out[OFF_SC + b * NTOP + tid] = topSc[b * NTOP + tid];
    __syncthreads();
    if (tid < NTOP) {
        float cx = refp[tid][0], cy = refp[tid][1], w = refp[tid][2], h = refp[tid][3];
        boxes[tid][0] = truncf((cx - 0.5f * w) * WH[b * 4 + 0]);
        boxes[tid][1] = truncf((cy - 0.5f * h) * WH[b * 4 + 1]);
        boxes[tid][2] = truncf((cx + 0.5f * w) * WH[b * 4 + 2]);
        boxes[tid][3] = truncf((cy + 0.5f * h) * WH[b * 4 + 3]);
    }
    __syncthreads();
    if (tid == 0) {
        bool supp[NTOP];
        float area[NTOP];
        for (int k = 0; k < NTOP; k++) {
            supp[k] = false;
            area[k] = (boxes[k][2] - boxes[k][0]) * (boxes[k][3] - boxes[k][1]);
        }
        for (int i = 0; i < NTOP; i++) {
            if (supp[i]) continue;
            for (int j = i + 1; j < NTOP; j++) {
                float xx1 = fmaxf(boxes[i][0], boxes[j][0]);
                float yy1 = fmaxf(boxes[i][1], boxes[j][1]);
                float xx2 = fminf(boxes[i][2], boxes[j][2]);
                float yy2 = fminf(boxes[i][3], boxes[j][3]);
                float inter = fmaxf(xx2 - xx1, 0.f) * fmaxf(yy2 - yy1, 0.f);
                float iou = inter / (area[i] + area[j] - inter);
                if (iou > 0.5f) supp[j] = true;
            }
        }
        for (int k = 0; k < NTOP; k++)
            out[OFF_KEEP + b * NTOP + k] = supp[k] ? 0.f : 1.f;
    }
}

// ---------------- launch -----------------------------------------------------
extern "C" void kernel_launch(void* const* d_in, const int* in_sizes, int n_in,
                              void* d_out, int out_size)
{
    const float* memory        = (const float*)d_in[0];
    const unsigned char* mask  = (const unsigned char*)d_in[1];
    const float* WH            = (const float*)d_in[2];
    const float* W_enc         = (const float*)d_in[3];
    const float* b_enc         = (const float*)d_in[4];
    const float* ln_g          = (const float*)d_in[5];
    const float* ln_b          = (const float*)d_in[6];
    const float* W_cls         = (const float*)d_in[7];
    const float* b_cls         = (const float*)d_in[8];
    const float* W1            = (const float*)d_in[9];
    const float* b1            = (const float*)d_in[10];
    const float* W2            = (const float*)d_in[11];
    const float* b2            = (const float*)d_in[12];
    const float* W3            = (const float*)d_in[13];
    const float* b3            = (const float*)d_in[14];
    float* out = (float*)d_out;

    float *p_outmem, *p_scores, *p_topsc, *p_ctop, *p_candV, *p_wpad, *p_toplog;
    int *p_topidx, *p_candI;
    cudaGetSymbolAddress((void**)&p_outmem,  g_outmem);
    cudaGetSymbolAddress((void**)&p_scores,  g_scores);
    cudaGetSymbolAddress((void**)&p_topidx,  g_topidx);
    cudaGetSymbolAddress((void**)&p_topsc,   g_topsc);
    cudaGetSymbolAddress((void**)&p_ctop,    g_ctop);
    cudaGetSymbolAddress((void**)&p_candV,   g_candV);
    cudaGetSymbolAddress((void**)&p_candI,   g_candI);
    cudaGetSymbolAddress((void**)&p_wpad,    g_wpad);
    cudaGetSymbolAddress((void**)&p_toplog,  g_toplog);

    cudaFuncSetAttribute(gemm_fused_kernel,
                         cudaFuncAttributeMaxDynamicSharedMemorySize, GL_SMEM_BYTES);

    const int gRows = (MROWS + 127) / 128;   // 1247
    // pad W_cls -> [256][96]
    wpad_kernel<<<(CH * NCP + 255) / 256, 256>>>(W_cls, p_wpad);
    // out_mem = LN(mem_masked @ W_enc + b_enc); scores = rowmax(out_mem@Wcls+b)
    gemm_fused_kernel<<<gRows, 512, GL_SMEM_BYTES>>>(memory, mask, W_enc, b_enc,
                                                     ln_g, ln_b, p_wpad, b_cls,
                                                     p_outmem, p_scores);
    // top-20 per batch (two-phase)
    topk1_kernel<<<dim3(CHUNKS, BSZ), 256>>>(p_scores, p_candV, p_candI);
    topk2_kernel<<<BSZ, 320>>>(p_candV, p_candI, p_topidx, p_topsc);
    // MLP + coords + logits only on the 160 selected rows
    tinymlp_kernel<<<BSZ * NTOP, 256>>>(p_outmem, mask, W1, b1, W2, b2, W3, b3,
                                        W_cls, b_cls, p_topidx, p_ctop, p_toplog);
    // gather + sigmoid + NMS + writes
    final_kernel<<<BSZ, 128>>>(p_toplog, p_ctop, p_topidx, p_topsc, WH, out);

    (void)in_sizes; (void)n_in; (void)out_size;
}